// round 11
// baseline (speedup 1.0000x reference)
#include <cuda_runtime.h>
#include <cuda_fp16.h>
#include <cstdint>

#define NFEAT   2048
#define NBATCH  8192
#define NFIELDS 8
#define FDIM    256
#define NL      64
#define ROWT    128
#define NTHREADS 256

// static device scratch (no runtime allocation)
__device__ __half g_xh[(size_t)NBATCH * NFEAT];               // 32 MB  [row][k]
__device__ __half g_vh[NFIELDS * NFIELDS * NL * FDIM];         // 2 MB   [s][t][l][k]
__device__ __half g_m[(size_t)NBATCH * NFIELDS * NFIELDS * NL];// 64 MB  [row][s][t][l]
__device__ float  g_dks[NFEAT];                                // sum_l V[k,f(k),l]^2 (fp16 vals)
__device__ float  g_diag[NBATCH];                              // sum_{s,l} M[s,s,l]^2 (fp32)

// ---------------- GEMM-pass SMEM: X resident 64KB + 2 W stage bufs = 96KB -> 2 CTAs/SM ----
#define SM_X 0
#define SM_W 65536
#define SM_TOTAL (65536 + 2 * 16384)   // 98304 B

#define SW128(off) ((off) ^ (((off) >> 3) & 0x70))

static __device__ __forceinline__ uint32_t smem_u32(const void* p) {
    uint32_t a;
    asm("{ .reg .u64 t; cvta.to.shared.u64 t, %1; cvt.u32.u64 %0, t; }" : "=r"(a) : "l"(p));
    return a;
}

#define CP_ASYNC16(dst, src) \
    asm volatile("cp.async.cg.shared.global [%0], [%1], 16;" :: "r"(dst), "l"(src))
#define CP_COMMIT() asm volatile("cp.async.commit_group;" ::: "memory")
#define CP_WAIT0()  asm volatile("cp.async.wait_group 0;" ::: "memory")
#define CP_WAIT1()  asm volatile("cp.async.wait_group 1;" ::: "memory")

static __device__ __forceinline__ void ldmx4(uint32_t addr, uint32_t& r0, uint32_t& r1,
                                             uint32_t& r2, uint32_t& r3) {
    asm volatile("ldmatrix.sync.aligned.m8n8.x4.shared.b16 {%0,%1,%2,%3}, [%4];"
                 : "=r"(r0), "=r"(r1), "=r"(r2), "=r"(r3) : "r"(addr));
}

static __device__ __forceinline__ void mma16816(float* d, uint32_t a0, uint32_t a1,
                                                uint32_t a2, uint32_t a3,
                                                uint32_t b0, uint32_t b1) {
    asm volatile(
        "mma.sync.aligned.m16n8k16.row.col.f32.f16.f16.f32 "
        "{%0,%1,%2,%3}, {%4,%5,%6,%7}, {%8,%9}, {%0,%1,%2,%3};"
        : "+f"(d[0]), "+f"(d[1]), "+f"(d[2]), "+f"(d[3])
        : "r"(a0), "r"(a1), "r"(a2), "r"(a3), "r"(b0), "r"(b1));
}

// ------------------------------------------------------------------
__global__ void k_convert_x(const float* __restrict__ x) {
    size_t i = (size_t)blockIdx.x * blockDim.x + threadIdx.x;  // 8 floats each
    size_t n8 = (size_t)NBATCH * NFEAT / 8;
    if (i < n8) {
        const float4* src = (const float4*)x;
        float4 f0 = src[2 * i], f1 = src[2 * i + 1];
        __half2 h0 = __floats2half2_rn(f0.x, f0.y);
        __half2 h1 = __floats2half2_rn(f0.z, f0.w);
        __half2 h2 = __floats2half2_rn(f1.x, f1.y);
        __half2 h3 = __floats2half2_rn(f1.z, f1.w);
        uint4 o;
        o.x = *(uint32_t*)&h0; o.y = *(uint32_t*)&h1;
        o.z = *(uint32_t*)&h2; o.w = *(uint32_t*)&h3;
        ((uint4*)g_xh)[i] = o;
    }
}

__global__ void k_convert_v(const float* __restrict__ V) {
    int idx = blockIdx.x * blockDim.x + threadIdx.x;
    if (idx < NBATCH) g_diag[idx] = 0.f;
    if (idx < NFEAT * NFIELDS * NL) {
        int i = idx / (NFIELDS * NL);
        int rest = idx % (NFIELDS * NL);
        int t = rest / NL, l = rest % NL;
        int s = i >> 8, k = i & 255;
        g_vh[(((s * NFIELDS + t) * NL) + l) * FDIM + k] = __float2half_rn(V[idx]);
    }
}

__global__ void k_dks() {
    int k = blockIdx.x * blockDim.x + threadIdx.x;
    if (k < NFEAT) {
        int s = k >> 8, kin = k & 255;
        const __half* vp = g_vh + (size_t)((s * NFIELDS + s) * NL) * FDIM + kin;
        float a = 0.f;
        #pragma unroll 8
        for (int l = 0; l < NL; ++l) {
            float f = __half2float(vp[(size_t)l * FDIM]);
            a += f * f;
        }
        g_dks[k] = a;
    }
}

// ------------------------------------------------------------------
// W stage loader: stage st = c*4 + q -> rows [c*128, +128) of W_s, k in [q*64, +64)
static __device__ __forceinline__ void load_w(uint32_t base, const __half* wsrc,
                                              int st, int tid) {
    const int c = st >> 2, q = st & 3;
    const char* gw = (const char*)(wsrc + (size_t)(c * 128) * FDIM + q * 64);
    #pragma unroll
    for (int it = 0; it < 4; ++it) {
        int idx = tid + it * NTHREADS;
        int row = idx >> 3, ci = idx & 7;
        CP_ASYNC16(base + SW128(row * 128 + ci * 16),
                   gw + (size_t)row * (FDIM * 2) + ci * 16);
    }
}

// stage GEMM: warp tile m32 x n64 x k64;  A from resident X chunk, B from W stage buf
static __device__ __forceinline__ void gemm_st(uint32_t sx, uint32_t sw,
                                               int pm, int pn, int lane,
                                               float acc[2][8][4]) {
    const int arow = pm * 32 + (lane & 15);
    const int ak = ((lane >> 4) << 3) * 2;
    const int brow = pn * 64 + ((lane >> 4) << 3) + (lane & 7);
    const int bk = (((lane >> 3) & 1) << 3) * 2;
    #pragma unroll
    for (int k4 = 0; k4 < 4; ++k4) {
        const int kb = k4 * 32;
        uint32_t a00, a01, a02, a03, a10, a11, a12, a13;
        ldmx4(sx + SW128(arow * 128 + kb + ak), a00, a01, a02, a03);
        ldmx4(sx + SW128((arow + 16) * 128 + kb + ak), a10, a11, a12, a13);
        #pragma unroll
        for (int vt = 0; vt < 4; ++vt) {
            uint32_t b0, b1, b2, b3;
            ldmx4(sw + SW128((brow + vt * 16) * 128 + kb + bk), b0, b1, b2, b3);
            mma16816(acc[0][2 * vt],     a00, a01, a02, a03, b0, b1);
            mma16816(acc[0][2 * vt + 1], a00, a01, a02, a03, b2, b3);
            mma16816(acc[1][2 * vt],     a10, a11, a12, a13, b0, b1);
            mma16816(acc[1][2 * vt + 1], a10, a11, a12, a13, b2, b3);
        }
    }
}

__global__ __launch_bounds__(NTHREADS, 2)
void ffm_gemm() {
    extern __shared__ char smem[];
    const uint32_t sb = smem_u32(smem);
    const int tid = threadIdx.x;
    const int wrp = tid >> 5, lane = tid & 31;
    const int pm = wrp >> 1, pn = wrp & 1;
    const int s = blockIdx.y;
    const int r0 = blockIdx.x * ROWT;

    // X_s tile: 128 rows x 256 k (FIELD s's columns!), 4 chunks of [128 x 128B] SW128
    {
        const char* gx = (const char*)(g_xh + (size_t)r0 * NFEAT + s * FDIM);
        #pragma unroll
        for (int it = 0; it < 16; ++it) {
            int idx = tid + it * NTHREADS;
            int row = idx >> 5, c = idx & 31;
            CP_ASYNC16(sb + SM_X + (c >> 3) * 16384 + SW128(row * 128 + (c & 7) * 16),
                       gx + (size_t)row * (NFEAT * 2) + c * 16);
        }
    }
    const __half* wsrc = g_vh + (size_t)s * (NFIELDS * NL) * FDIM;   // [512 x 256]
    load_w(sb + SM_W, wsrc, 0, tid);             CP_COMMIT();  // c0 = X + W stage0 -> buf0
    load_w(sb + SM_W + 16384, wsrc, 1, tid);     CP_COMMIT();  // c1 = W stage1 -> buf1

    float acc[2][8][4];
    #pragma unroll
    for (int m = 0; m < 2; ++m)
        #pragma unroll
        for (int n = 0; n < 8; ++n)
            #pragma unroll
            for (int j = 0; j < 4; ++j) acc[m][n][j] = 0.f;

    for (int st = 0; st < 16; ++st) {
        if (st == 15) { CP_WAIT0(); } else { CP_WAIT1(); }   // stage st's group complete
        __syncthreads();                                     // ...and visible to all warps

        gemm_st(sb + SM_X + (st & 3) * 16384, sb + SM_W + (st & 1) * 16384, pm, pn, lane, acc);

        if ((st & 3) == 3) {
            // n-chunk c complete: write M (fp16), handle diag, reset accs
            const int c = st >> 2;
            const int colbase = c * 128 + pn * 64;
            const size_t rb0 = (size_t)r0 + pm * 32 + (lane >> 2);
            #pragma unroll
            for (int mf = 0; mf < 2; ++mf)
                #pragma unroll
                for (int nf = 0; nf < 8; ++nf) {
                    __half2 lo = __floats2half2_rn(acc[mf][nf][0], acc[mf][nf][1]);
                    __half2 hi = __floats2half2_rn(acc[mf][nf][2], acc[mf][nf][3]);
                    int col = colbase + nf * 8 + (lane & 3) * 2;
                    size_t r = rb0 + mf * 16;
                    *(uint32_t*)(g_m + r * 4096 + s * 512 + col)       = *(uint32_t*)&lo;
                    *(uint32_t*)(g_m + (r + 8) * 4096 + s * 512 + col) = *(uint32_t*)&hi;
                }
            if (c == (s >> 1) && pn == (s & 1)) {
                // this warp's n-half is exactly t == s: fp32 sum_l M_ss^2
                float d[4] = {0.f, 0.f, 0.f, 0.f};
                #pragma unroll
                for (int mf = 0; mf < 2; ++mf)
                    #pragma unroll
                    for (int nf = 0; nf < 8; ++nf) {
                        d[mf * 2 + 0] += acc[mf][nf][0] * acc[mf][nf][0] +
                                         acc[mf][nf][1] * acc[mf][nf][1];
                        d[mf * 2 + 1] += acc[mf][nf][2] * acc[mf][nf][2] +
                                         acc[mf][nf][3] * acc[mf][nf][3];
                    }
                #pragma unroll
                for (int i = 0; i < 4; ++i) {
                    d[i] += __shfl_xor_sync(0xFFFFFFFFu, d[i], 1);
                    d[i] += __shfl_xor_sync(0xFFFFFFFFu, d[i], 2);
                }
                if ((lane & 3) == 0) {
                    #pragma unroll
                    for (int mf = 0; mf < 2; ++mf)
                        #pragma unroll
                        for (int h = 0; h < 2; ++h)
                            atomicAdd(g_diag + rb0 + mf * 16 + h * 8, d[mf * 2 + h]);
                }
            }
            #pragma unroll
            for (int m = 0; m < 2; ++m)
                #pragma unroll
                for (int n = 0; n < 8; ++n)
                    #pragma unroll
                    for (int j = 0; j < 4; ++j) acc[m][n][j] = 0.f;
        }

        if (st + 2 < 16) {
            __syncthreads();   // all warps done reading buf (st&1) before overwrite
            load_w(sb + SM_W + (st & 1) * 16384, wsrc, st + 2, tid);
            CP_COMMIT();
        }
    }
}

// ------------------------------------------------------------------
__global__ __launch_bounds__(256)
void ffm_epi(const float* __restrict__ w, const float* __restrict__ b,
             float* __restrict__ out) {
    const int row = blockIdx.x * 8 + (threadIdx.x >> 5);
    const int lane = threadIdx.x & 31;

    // load M row: a[s*8+t] = half2 at l = {lane*2, lane*2+1}
    const uint32_t* mr = (const uint32_t*)(g_m + (size_t)row * 4096);
    uint32_t a[64];
    #pragma unroll
    for (int st = 0; st < 64; ++st) a[st] = mr[st * 32 + lane];

    float inter = 0.f;
    #pragma unroll
    for (int s2 = 0; s2 < 8; ++s2)
        #pragma unroll
        for (int t2 = s2 + 1; t2 < 8; ++t2) {
            float2 pa = __half22float2(*(const __half2*)&a[s2 * 8 + t2]);
            float2 pb = __half22float2(*(const __half2*)&a[t2 * 8 + s2]);
            inter += pa.x * pb.x + pa.y * pb.y;
        }
    inter *= 2.f;

    // q + linear from fp16 x (same values the GEMM consumed)
    float qv = 0.f, lin = 0.f;
    const __half2* xr = (const __half2*)(g_xh + (size_t)row * NFEAT);
    const float2* dk2 = (const float2*)g_dks;
    const float2* w2 = (const float2*)w;
    #pragma unroll 8
    for (int i = 0; i < 32; ++i) {
        int k2 = i * 32 + lane;
        float2 f = __half22float2(xr[k2]);
        float2 d = dk2[k2];
        float2 wv = w2[k2];
        qv += f.x * f.x * d.x + f.y * f.y * d.y;
        lin += f.x * wv.x + f.y * wv.y;
    }

    float v = lin + 0.25f * (inter - qv);
    #pragma unroll
    for (int off = 16; off > 0; off >>= 1)
        v += __shfl_xor_sync(0xFFFFFFFFu, v, off);
    if (lane == 0)
        out[row] = b[0] + v + 0.25f * g_diag[row];
}

// ------------------------------------------------------------------
extern "C" void kernel_launch(void* const* d_in, const int* in_sizes, int n_in,
                              void* d_out, int out_size) {
    const float* x = (const float*)d_in[0];
    const float* b = (const float*)d_in[1];
    const float* w = (const float*)d_in[2];
    const float* V = (const float*)d_in[3];
    float* out = (float*)d_out;

    cudaFuncSetAttribute(ffm_gemm, cudaFuncAttributeMaxDynamicSharedMemorySize, SM_TOTAL);

    {
        size_t n8 = (size_t)NBATCH * NFEAT / 8;
        k_convert_x<<<(unsigned)((n8 + 255) / 256), 256>>>(x);
    }
    k_convert_v<<<(NFEAT * NFIELDS * NL + 255) / 256, 256>>>(V);
    k_dks<<<(NFEAT + 255) / 256, 256>>>();
    ffm_gemm<<<dim3(NBATCH / ROWT, NFIELDS), NTHREADS, SM_TOTAL>>>();
    ffm_epi<<<NBATCH / 8, 256>>>(w, b, out);
}

// round 12
// speedup vs baseline: 1.0876x; 1.0876x over previous
#include <cuda_runtime.h>
#include <cuda_fp16.h>
#include <cstdint>

#define NFEAT   2048
#define NBATCH  8192
#define NFIELDS 8
#define FDIM    256
#define NL      64
#define ROWT    128
#define NTHREADS 256

// fp16 scratch (static device arrays -- no runtime allocation)
__device__ __half g_xh[(size_t)NBATCH * NFEAT];              // 32 MB, row-major [B, F]
__device__ __half g_vh[NFIELDS * NFIELDS * NL * FDIM];        // 2 MB, [s][t][l][k]

// ---------------- SMEM layout (65 KB -> 3 CTAs/SM) ----------------
// X: 2 k-quarter bufs [128 rows x 128B] = 16 KB each (single interleaved stream)
// VS/VT: 2 bufs x 2 h-halves x [32 l-rows x 128B] = 4 KB per (buf,h)
#define SM_DKS  0
#define SM_X    1024
#define SM_VS   (SM_X + 32768)
#define SM_VT   (SM_VS + 16384)
#define SM_TOTAL (SM_VT + 16384)   // 66560 B

#define SW128(off) ((off) ^ (((off) >> 3) & 0x70))

static __device__ __forceinline__ uint32_t smem_u32(const void* p) {
    uint32_t a;
    asm("{ .reg .u64 t; cvta.to.shared.u64 t, %1; cvt.u32.u64 %0, t; }" : "=r"(a) : "l"(p));
    return a;
}

#define CP_ASYNC16(dst, src) \
    asm volatile("cp.async.cg.shared.global [%0], [%1], 16;" :: "r"(dst), "l"(src))
#define CP_COMMIT() asm volatile("cp.async.commit_group;" ::: "memory")
#define CP_WAIT0()  asm volatile("cp.async.wait_group 0;" ::: "memory")
#define CP_WAIT1()  asm volatile("cp.async.wait_group 1;" ::: "memory")

static __device__ __forceinline__ void ldmx4(uint32_t addr, uint32_t& r0, uint32_t& r1,
                                             uint32_t& r2, uint32_t& r3) {
    asm volatile("ldmatrix.sync.aligned.m8n8.x4.shared.b16 {%0,%1,%2,%3}, [%4];"
                 : "=r"(r0), "=r"(r1), "=r"(r2), "=r"(r3) : "r"(addr));
}

static __device__ __forceinline__ void mma16816(float* d, uint32_t a0, uint32_t a1,
                                                uint32_t a2, uint32_t a3,
                                                uint32_t b0, uint32_t b1) {
    asm volatile(
        "mma.sync.aligned.m16n8k16.row.col.f32.f16.f16.f32 "
        "{%0,%1,%2,%3}, {%4,%5,%6,%7}, {%8,%9}, {%0,%1,%2,%3};"
        : "+f"(d[0]), "+f"(d[1]), "+f"(d[2]), "+f"(d[3])
        : "r"(a0), "r"(a1), "r"(a2), "r"(a3), "r"(b0), "r"(b1));
}

// Balanced unit groups: g0 = 4 pairs; g1..g8 = 3 pairs + 1 diag
__device__ const signed char U_S[36] = {
    0,0,0,0,  0,0,0,0,  1,1,1,1,  1,1,1,2,  2,2,2,3,  2,2,3,4,  3,3,3,5,  4,4,4,6,  5,5,6,7};
__device__ const signed char U_T[36] = {
    1,2,3,4,  5,6,7,0,  2,3,4,1,  5,6,7,2,  3,4,5,3,  6,7,4,4,  5,6,7,5,  5,6,7,6,  6,7,7,7};

// ------------------------------------------------------------------
__global__ void k_convert_x(const float* __restrict__ x) {
    size_t i = (size_t)blockIdx.x * blockDim.x + threadIdx.x;  // 8 floats each
    size_t n8 = (size_t)NBATCH * NFEAT / 8;
    if (i < n8) {
        const float4* src = (const float4*)x;
        float4 f0 = src[2 * i], f1 = src[2 * i + 1];
        __half2 h0 = __floats2half2_rn(f0.x, f0.y);
        __half2 h1 = __floats2half2_rn(f0.z, f0.w);
        __half2 h2 = __floats2half2_rn(f1.x, f1.y);
        __half2 h3 = __floats2half2_rn(f1.z, f1.w);
        uint4 o;
        o.x = *(uint32_t*)&h0; o.y = *(uint32_t*)&h1;
        o.z = *(uint32_t*)&h2; o.w = *(uint32_t*)&h3;
        ((uint4*)g_xh)[i] = o;
    }
}

__global__ void k_convert_v(const float* __restrict__ V, const float* __restrict__ b,
                            float* __restrict__ out) {
    int idx = blockIdx.x * blockDim.x + threadIdx.x;
    if (idx < NBATCH) out[idx] = b[0];
    if (idx < NFEAT * NFIELDS * NL) {
        int i = idx / (NFIELDS * NL);
        int rest = idx % (NFIELDS * NL);
        int t = rest / NL, l = rest % NL;
        int s = i >> 8, k = i & 255;
        g_vh[(((s * NFIELDS + t) * NL) + l) * FDIM + k] = __float2half_rn(V[idx]);
    }
}

// ------------------------------------------------------------------
// X quarter slice for this thread's pair: rows p*32+h*16..+16 x 128B; 4 x 16B per thread
static __device__ __forceinline__ void load_xq(uint32_t sbuf, const __half* gsrc,
                                               int p, int h, int lane) {
    #pragma unroll
    for (int it = 0; it < 4; ++it) {
        int tsk = lane + it * 32;                 // 0..127
        int row = p * 32 + h * 16 + (tsk >> 3);
        int c = tsk & 7;
        uint32_t sa = sbuf + SW128(row * 128 + c * 16);
        const char* ga = (const char*)gsrc + (size_t)row * (NFEAT * 2) + c * 16;
        CP_ASYNC16(sa, ga);
    }
}

// V half-quarter for this h-group: 32 l-rows x 128B; 2 x 16B per thread
// gsrc pre-offset to [l = h*32][k = q*64]
static __device__ __forceinline__ void load_vq(uint32_t sbuf, const __half* gsrc,
                                               int p, int lane) {
    #pragma unroll
    for (int it = 0; it < 2; ++it) {
        int tsk = p * 32 + lane + it * 128;       // 0..255, disjoint across h-group
        int row = tsk >> 3;
        int c = tsk & 7;
        uint32_t sa = sbuf + SW128(row * 128 + c * 16);
        const char* ga = (const char*)gsrc + (size_t)row * (FDIM * 2) + c * 16;
        CP_ASYNC16(sa, ga);
    }
}

// Quarter GEMM: acc += X_q(warp's 32 rows x 64k) @ V_halfq^T   (m32 x n32 x k64)
static __device__ __forceinline__ void gemm32(uint32_t sx, uint32_t sv,
                                              int p, int lane, float acc[2][4][4]) {
    const int arow = p * 32 + (lane & 15);
    const int ak = ((lane >> 4) << 3) * 2;
    const int brow = ((lane >> 4) << 3) + (lane & 7);
    const int bk = (((lane >> 3) & 1) << 3) * 2;
    #pragma unroll
    for (int k4 = 0; k4 < 4; ++k4) {
        const int kb = k4 * 32;
        uint32_t a00, a01, a02, a03, a10, a11, a12, a13;
        ldmx4(sx + SW128(arow * 128 + kb + ak), a00, a01, a02, a03);
        ldmx4(sx + SW128((arow + 16) * 128 + kb + ak), a10, a11, a12, a13);
        #pragma unroll
        for (int vt = 0; vt < 2; ++vt) {
            uint32_t b0, b1, b2, b3;
            ldmx4(sv + SW128((vt * 16 + brow) * 128 + kb + bk), b0, b1, b2, b3);
            mma16816(acc[0][2 * vt],     a00, a01, a02, a03, b0, b1);
            mma16816(acc[0][2 * vt + 1], a00, a01, a02, a03, b2, b3);
            mma16816(acc[1][2 * vt],     a10, a11, a12, a13, b0, b1);
            mma16816(acc[1][2 * vt + 1], a10, a11, a12, a13, b2, b3);
        }
    }
}

static __device__ __forceinline__ void zero4(float acc[2][4][4]) {
    #pragma unroll
    for (int m = 0; m < 2; ++m)
        #pragma unroll
        for (int n = 0; n < 4; ++n)
            #pragma unroll
            for (int j = 0; j < 4; ++j) acc[m][n][j] = 0.f;
}

__global__ __launch_bounds__(NTHREADS, 3)
void ffm_main(const float* __restrict__ w, float* __restrict__ out) {
    extern __shared__ char smem[];
    const uint32_t sb = smem_u32(smem);
    const int tid = threadIdx.x;
    const int wrp = tid >> 5;
    const int lane = tid & 31;
    const int p = wrp >> 1;          // pair (m-tile) 0..3
    const int h = wrp & 1;           // n-half 0..1
    const int r0 = blockIdx.x * ROWT;
    float* dks = (float*)(smem + SM_DKS);

    float acc_int[4] = {0.f, 0.f, 0.f, 0.f};   // row = p*32 + (lane>>2) + slot*8

    for (int uu = 0; uu < 4; ++uu) {
        const int u = blockIdx.y * 4 + uu;
        const int s = U_S[u], t = U_T[u];
        const __half* xs = g_xh + (size_t)r0 * NFEAT + s * FDIM;
        const __half* xt = g_xh + (size_t)r0 * NFEAT + t * FDIM;
        const __half* vst = g_vh + (size_t)((s * NFIELDS + t) * NL + h * 32) * FDIM;
        const __half* vts = g_vh + (size_t)((t * NFIELDS + s) * NL + h * 32) * FDIM;

        float acc[2][4][4];
        zero4(acc);
        float p4[4] = {0.f, 0.f, 0.f, 0.f};

        if (s != t) {
            uint32_t m1[2][4][2];   // fp16 stash of GEMM1 (16 regs)

            // prologue: stages 0,1 = Xs.q0/q1 + Vst.q0/q1
            load_xq(sb + SM_X, xs, p, h, lane);
            load_vq(sb + SM_VS + h * 4096, vst, p, lane);
            CP_COMMIT();
            load_xq(sb + SM_X + 16384, xs + 64, p, h, lane);
            load_vq(sb + SM_VS + (2 + h) * 4096, vst + 64, p, lane);
            CP_COMMIT();

            // 8 stages: st 0-3 = Xs quarters (GEMM1), st 4-7 = Xt quarters (GEMM2)
            #pragma unroll
            for (int st = 0; st < 8; ++st) {
                if (st == 7) { CP_WAIT0(); } else { CP_WAIT1(); }
                __syncthreads();                 // stage st visible to all warps

                gemm32(sb + SM_X + (st & 1) * 16384,
                       (st < 4 ? sb + SM_VS : sb + SM_VT) + ((st & 1) * 2 + h) * 4096,
                       p, lane, acc);

                if (st == 3) {
                    // GEMM1 complete: pack M1 -> fp16 regs, reset acc for GEMM2
                    #pragma unroll
                    for (int mf = 0; mf < 2; ++mf)
                        #pragma unroll
                        for (int nf = 0; nf < 4; ++nf) {
                            __half2 lo = __floats2half2_rn(acc[mf][nf][0], acc[mf][nf][1]);
                            __half2 hi = __floats2half2_rn(acc[mf][nf][2], acc[mf][nf][3]);
                            m1[mf][nf][0] = *(uint32_t*)&lo;
                            m1[mf][nf][1] = *(uint32_t*)&hi;
                            acc[mf][nf][0] = 0.f; acc[mf][nf][1] = 0.f;
                            acc[mf][nf][2] = 0.f; acc[mf][nf][3] = 0.f;
                        }
                }

                __syncthreads();                 // readers done; buffers free
                if (st < 6) {
                    const int j = st + 2;        // stage to prefetch
                    const int q = (j < 4) ? j : j - 4;
                    const __half* xsrc = (j < 4) ? xs : xt;
                    const __half* vsrc = (j < 4) ? vst : vts;
                    uint32_t vbase = (j < 4) ? sb + SM_VS : sb + SM_VT;
                    load_xq(sb + SM_X + (j & 1) * 16384, xsrc + q * 64, p, h, lane);
                    load_vq(vbase + ((j & 1) * 2 + h) * 4096, vsrc + q * 64, p, lane);
                    CP_COMMIT();
                }
            }

            // dot(M1, M2) over this warp's n-half, counted twice (ordered pairs)
            #pragma unroll
            for (int mf = 0; mf < 2; ++mf)
                #pragma unroll
                for (int nf = 0; nf < 4; ++nf) {
                    float2 lo = __half22float2(*(__half2*)&m1[mf][nf][0]);
                    float2 hi = __half22float2(*(__half2*)&m1[mf][nf][1]);
                    p4[mf * 2 + 0] += lo.x * acc[mf][nf][0] + lo.y * acc[mf][nf][1];
                    p4[mf * 2 + 1] += hi.x * acc[mf][nf][2] + hi.y * acc[mf][nf][3];
                }
            #pragma unroll
            for (int i = 0; i < 4; ++i) p4[i] *= 2.f;
        } else {
            // ---- diag unit ----
            // dks[k] = sum_l V_ss[l,k]^2 from global fp16 (same values the GEMM uses)
            {
                const __half* vp = g_vh + (size_t)((s * NFIELDS + s) * NL) * FDIM + tid;
                float a = 0.f;
                #pragma unroll 8
                for (int l = 0; l < NL; ++l) {
                    float f = __half2float(vp[(size_t)l * FDIM]);
                    a += f * f;
                }
                dks[tid] = a;
            }

            load_xq(sb + SM_X, xs, p, h, lane);
            load_vq(sb + SM_VS + h * 4096, vst, p, lane);
            CP_COMMIT();
            load_xq(sb + SM_X + 16384, xs + 64, p, h, lane);
            load_vq(sb + SM_VS + (2 + h) * 4096, vst + 64, p, lane);
            CP_COMMIT();

            float dql[4] = {0.f, 0.f, 0.f, 0.f};
            const float* wp = w + s * FDIM;
            #pragma unroll
            for (int q = 0; q < 4; ++q) {
                if (q == 3) { CP_WAIT0(); } else { CP_WAIT1(); }
                __syncthreads();                 // stage q visible; dks visible (q==0)

                gemm32(sb + SM_X + (q & 1) * 16384,
                       sb + SM_VS + ((q & 1) * 2 + h) * 4096, p, lane, acc);

                // q + linear for this quarter (k-split by h, rows of own pair)
                {
                    const char* xsm = smem + SM_X + (q & 1) * 16384;
                    const int kin0 = h * 32 + (lane & 3) * 8;
                    const int rb = p * 32 + (lane >> 2);
                    const float* dq = dks + q * 64;
                    const float* wq = wp + q * 64;
                    #pragma unroll
                    for (int i = 0; i < 8; ++i) {
                        int k = kin0 + i;
                        float dk = dq[k];
                        float wv = __ldg(wq + k);
                        #pragma unroll
                        for (int sl = 0; sl < 4; ++sl) {
                            float xv = __half2float(*(const __half*)(
                                xsm + SW128((rb + sl * 8) * 128 + k * 2)));
                            dql[sl] += xv * (4.f * wv - xv * dk);
                        }
                    }
                }

                __syncthreads();
                if (q < 2) {
                    load_xq(sb + SM_X + (q & 1) * 16384, xs + (q + 2) * 64, p, h, lane);
                    load_vq(sb + SM_VS + ((q & 1) * 2 + h) * 4096, vst + (q + 2) * 64,
                            p, lane);
                    CP_COMMIT();
                }
            }

            // self dot - q + 4*linear
            #pragma unroll
            for (int mf = 0; mf < 2; ++mf)
                #pragma unroll
                for (int nf = 0; nf < 4; ++nf) {
                    p4[mf * 2 + 0] += acc[mf][nf][0] * acc[mf][nf][0] +
                                      acc[mf][nf][1] * acc[mf][nf][1];
                    p4[mf * 2 + 1] += acc[mf][nf][2] * acc[mf][nf][2] +
                                      acc[mf][nf][3] * acc[mf][nf][3];
                }
            #pragma unroll
            for (int i = 0; i < 4; ++i) p4[i] += dql[i];
        }

        // reduce over 4 lanes sharing each row; accumulate
        #pragma unroll
        for (int i = 0; i < 4; ++i) {
            p4[i] += __shfl_xor_sync(0xFFFFFFFFu, p4[i], 1);
            p4[i] += __shfl_xor_sync(0xFFFFFFFFu, p4[i], 2);
            acc_int[i] += p4[i];
        }
    }

    if ((lane & 3) == 0) {
        #pragma unroll
        for (int sl = 0; sl < 4; ++sl) {
            int row = r0 + p * 32 + (lane >> 2) + sl * 8;
            atomicAdd(out + row, 0.25f * acc_int[sl]);
        }
    }
}

// ------------------------------------------------------------------
extern "C" void kernel_launch(void* const* d_in, const int* in_sizes, int n_in,
                              void* d_out, int out_size) {
    const float* x = (const float*)d_in[0];
    const float* b = (const float*)d_in[1];
    const float* w = (const float*)d_in[2];
    const float* V = (const float*)d_in[3];
    float* out = (float*)d_out;

    cudaFuncSetAttribute(ffm_main, cudaFuncAttributeMaxDynamicSharedMemorySize, SM_TOTAL);

    {
        size_t n8 = (size_t)NBATCH * NFEAT / 8;
        k_convert_x<<<(unsigned)((n8 + 255) / 256), 256>>>(x);
    }
    k_convert_v<<<(NFEAT * NFIELDS * NL + 255) / 256, 256>>>(V, b, out);
    ffm_main<<<dim3(NBATCH / ROWT, 9), NTHREADS, SM_TOTAL>>>(w, out);
}

// round 13
// speedup vs baseline: 1.1388x; 1.0471x over previous
#include <cuda_runtime.h>
#include <cuda_fp16.h>
#include <cstdint>

#define NFEAT   2048
#define NBATCH  8192
#define NFIELDS 8
#define FDIM    256
#define NL      64
#define ROWT    128
#define NTHREADS 256

// fp16 V scratch (static device array -- no runtime allocation)
__device__ __half g_vh[NFIELDS * NFIELDS * NL * FDIM];        // 2 MB, [s][t][l][k]

// ---------------- SMEM layout (97 KB -> 2 CTAs/SM) ----------------
// XS/XT: 2 k-quarter bufs x [128 rows x 128B] = 16 KB each buf
// VS/VT: 2 bufs x 2 h-halves x [32 l-rows x 128B] = 4 KB per (buf,h)
#define SM_DKS  0
#define SM_XS   1024
#define SM_XT   (SM_XS + 32768)
#define SM_VS   (SM_XT + 32768)
#define SM_VT   (SM_VS + 16384)
#define SM_TOTAL (SM_VT + 16384)   // 99328 B

#define SW128(off) ((off) ^ (((off) >> 3) & 0x70))

static __device__ __forceinline__ uint32_t smem_u32(const void* p) {
    uint32_t a;
    asm("{ .reg .u64 t; cvta.to.shared.u64 t, %1; cvt.u32.u64 %0, t; }" : "=r"(a) : "l"(p));
    return a;
}

#define CP_ASYNC16(dst, src) \
    asm volatile("cp.async.cg.shared.global [%0], [%1], 16;" :: "r"(dst), "l"(src))
#define CP_COMMIT() asm volatile("cp.async.commit_group;" ::: "memory")
#define CP_WAIT0()  asm volatile("cp.async.wait_group 0;" ::: "memory")
#define CP_WAIT1()  asm volatile("cp.async.wait_group 1;" ::: "memory")

#define STS128(sa, r0, r1, r2, r3) \
    asm volatile("st.shared.v4.b32 [%0], {%1,%2,%3,%4};" \
                 :: "r"(sa), "r"(r0), "r"(r1), "r"(r2), "r"(r3) : "memory")

// named barriers: 1+p (64 thr, pair scope), 5+h (128 thr, h-group scope)
#define BARX(id, cnt) asm volatile("bar.sync %0, %1;" :: "r"(id), "r"(cnt) : "memory")

static __device__ __forceinline__ void ldmx4(uint32_t addr, uint32_t& r0, uint32_t& r1,
                                             uint32_t& r2, uint32_t& r3) {
    asm volatile("ldmatrix.sync.aligned.m8n8.x4.shared.b16 {%0,%1,%2,%3}, [%4];"
                 : "=r"(r0), "=r"(r1), "=r"(r2), "=r"(r3) : "r"(addr));
}

static __device__ __forceinline__ void mma16816(float* d, uint32_t a0, uint32_t a1,
                                                uint32_t a2, uint32_t a3,
                                                uint32_t b0, uint32_t b1) {
    asm volatile(
        "mma.sync.aligned.m16n8k16.row.col.f32.f16.f16.f32 "
        "{%0,%1,%2,%3}, {%4,%5,%6,%7}, {%8,%9}, {%0,%1,%2,%3};"
        : "+f"(d[0]), "+f"(d[1]), "+f"(d[2]), "+f"(d[3])
        : "r"(a0), "r"(a1), "r"(a2), "r"(a3), "r"(b0), "r"(b1));
}

// Balanced unit groups: g0 = 4 pairs; g1..g8 = 3 pairs + 1 diag
__device__ const signed char U_S[36] = {
    0,0,0,0,  0,0,0,0,  1,1,1,1,  1,1,1,2,  2,2,2,3,  2,2,3,4,  3,3,3,5,  4,4,4,6,  5,5,6,7};
__device__ const signed char U_T[36] = {
    1,2,3,4,  5,6,7,0,  2,3,4,1,  5,6,7,2,  3,4,5,3,  6,7,4,4,  5,6,7,5,  5,6,7,6,  6,7,7,7};

// ------------------------------------------------------------------
__global__ void k_convert_v(const float* __restrict__ V, const float* __restrict__ b,
                            float* __restrict__ out) {
    int idx = blockIdx.x * blockDim.x + threadIdx.x;
    if (idx < NBATCH) out[idx] = b[0];
    if (idx < NFEAT * NFIELDS * NL) {
        int i = idx / (NFIELDS * NL);
        int rest = idx % (NFIELDS * NL);
        int t = rest / NL, l = rest % NL;
        int s = i >> 8, k = i & 255;
        g_vh[(((s * NFIELDS + t) * NL) + l) * FDIM + k] = __float2half_rn(V[idx]);
    }
}

// ------------------------------------------------------------------
// X quarter slice, f32 -> fp16 convert inline: rows p*32+h*16..+16 x 64 k
// gsrc pre-offset to [row r0][field column base + q*64] in f32 x.
static __device__ __forceinline__ void load_xq_cvt(uint32_t sbuf, const float* gsrc,
                                                   int p, int h, int lane) {
    #pragma unroll
    for (int it = 0; it < 4; ++it) {
        int tsk = lane + it * 32;                 // 0..127
        int row = p * 32 + h * 16 + (tsk >> 3);
        int c = tsk & 7;                          // 8 halves = 8 f32 per task
        const float4* ga = (const float4*)(gsrc + (size_t)row * NFEAT + c * 8);
        float4 f0 = __ldg(ga);
        float4 f1 = __ldg(ga + 1);
        __half2 h0 = __floats2half2_rn(f0.x, f0.y);
        __half2 h1 = __floats2half2_rn(f0.z, f0.w);
        __half2 h2 = __floats2half2_rn(f1.x, f1.y);
        __half2 h3 = __floats2half2_rn(f1.z, f1.w);
        uint32_t sa = sbuf + SW128(row * 128 + c * 16);
        STS128(sa, *(uint32_t*)&h0, *(uint32_t*)&h1, *(uint32_t*)&h2, *(uint32_t*)&h3);
    }
}

// V half-quarter for this h-group: 32 l-rows x 128B; 2 x 16B per thread (cp.async)
// gsrc pre-offset to [l = h*32][k = q*64]
static __device__ __forceinline__ void load_vq(uint32_t sbuf, const __half* gsrc,
                                               int p, int lane) {
    #pragma unroll
    for (int it = 0; it < 2; ++it) {
        int tsk = p * 32 + lane + it * 128;       // 0..255, disjoint across h-group
        int row = tsk >> 3;
        int c = tsk & 7;
        uint32_t sa = sbuf + SW128(row * 128 + c * 16);
        const char* ga = (const char*)gsrc + (size_t)row * (FDIM * 2) + c * 16;
        CP_ASYNC16(sa, ga);
    }
}

// Quarter GEMM: acc += X_q(warp's 32 rows x 64k) @ V_halfq^T   (m32 x n32 x k64)
static __device__ __forceinline__ void gemm32(uint32_t sx, uint32_t sv,
                                              int p, int lane, float acc[2][4][4]) {
    const int arow = p * 32 + (lane & 15);
    const int ak = ((lane >> 4) << 3) * 2;
    const int brow = ((lane >> 4) << 3) + (lane & 7);
    const int bk = (((lane >> 3) & 1) << 3) * 2;
    #pragma unroll
    for (int k4 = 0; k4 < 4; ++k4) {
        const int kb = k4 * 32;
        uint32_t a00, a01, a02, a03, a10, a11, a12, a13;
        ldmx4(sx + SW128(arow * 128 + kb + ak), a00, a01, a02, a03);
        ldmx4(sx + SW128((arow + 16) * 128 + kb + ak), a10, a11, a12, a13);
        #pragma unroll
        for (int vt = 0; vt < 2; ++vt) {
            uint32_t b0, b1, b2, b3;
            ldmx4(sv + SW128((vt * 16 + brow) * 128 + kb + bk), b0, b1, b2, b3);
            mma16816(acc[0][2 * vt],     a00, a01, a02, a03, b0, b1);
            mma16816(acc[0][2 * vt + 1], a00, a01, a02, a03, b2, b3);
            mma16816(acc[1][2 * vt],     a10, a11, a12, a13, b0, b1);
            mma16816(acc[1][2 * vt + 1], a10, a11, a12, a13, b2, b3);
        }
    }
}

static __device__ __forceinline__ void zero4(float acc[2][4][4]) {
    #pragma unroll
    for (int m = 0; m < 2; ++m)
        #pragma unroll
        for (int n = 0; n < 4; ++n)
            #pragma unroll
            for (int j = 0; j < 4; ++j) acc[m][n][j] = 0.f;
}

__global__ __launch_bounds__(NTHREADS, 2)
void ffm_main(const float* __restrict__ x, const float* __restrict__ w,
              float* __restrict__ out) {
    extern __shared__ char smem[];
    const uint32_t sb = smem_u32(smem);
    const int tid = threadIdx.x;
    const int wrp = tid >> 5;
    const int lane = tid & 31;
    const int p = wrp >> 1;          // pair (m-tile) 0..3
    const int h = wrp & 1;           // n-half 0..1
    const int r0 = blockIdx.x * ROWT;
    float* dks = (float*)(smem + SM_DKS);

    const int bar_p = 1 + p, bar_h = 5 + h;

    float acc_int[4] = {0.f, 0.f, 0.f, 0.f};   // row = p*32 + (lane>>2) + slot*8

    for (int uu = 0; uu < 4; ++uu) {
        const int u = blockIdx.y * 4 + uu;
        const int s = U_S[u], t = U_T[u];
        const float* xs = x + (size_t)r0 * NFEAT + s * FDIM;   // f32, converted inline
        const float* xt = x + (size_t)r0 * NFEAT + t * FDIM;
        const __half* vst = g_vh + (size_t)((s * NFIELDS + t) * NL + h * 32) * FDIM;
        const __half* vts = g_vh + (size_t)((t * NFIELDS + s) * NL + h * 32) * FDIM;

        float a1[2][4][4];
        zero4(a1);
        float p4[4] = {0.f, 0.f, 0.f, 0.f};

        if (s != t) {
            float a2[2][4][4];
            zero4(a2);
            // prologue: V quarters 0,1 async; X quarters 0,1 via LDG+cvt+STS
            load_vq(sb + SM_VS + h * 4096, vst, p, lane);
            load_vq(sb + SM_VT + h * 4096, vts, p, lane);
            CP_COMMIT();                                        // V stage 0
            load_vq(sb + SM_VS + (2 + h) * 4096, vst + 64, p, lane);
            load_vq(sb + SM_VT + (2 + h) * 4096, vts + 64, p, lane);
            CP_COMMIT();                                        // V stage 1
            load_xq_cvt(sb + SM_XS, xs, p, h, lane);
            load_xq_cvt(sb + SM_XT, xt, p, h, lane);
            load_xq_cvt(sb + SM_XS + 16384, xs + 64, p, h, lane);
            load_xq_cvt(sb + SM_XT + 16384, xt + 64, p, h, lane);

            #pragma unroll
            for (int q = 0; q < 4; ++q) {
                if (q == 3) { CP_WAIT0(); } else { CP_WAIT1(); }
                __syncwarp();
                BARX(bar_p, 64); BARX(bar_h, 128);      // quarter q visible everywhere
                const int bf = q & 1;
                gemm32(sb + SM_XS + bf * 16384, sb + SM_VS + (bf * 2 + h) * 4096, p, lane, a1);
                gemm32(sb + SM_XT + bf * 16384, sb + SM_VT + (bf * 2 + h) * 4096, p, lane, a2);
                if (q < 2) {
                    BARX(bar_p, 64); BARX(bar_h, 128);  // co-owners done reading buf
                    load_xq_cvt(sb + SM_XS + bf * 16384, xs + (q + 2) * 64, p, h, lane);
                    load_xq_cvt(sb + SM_XT + bf * 16384, xt + (q + 2) * 64, p, h, lane);
                    load_vq(sb + SM_VS + (bf * 2 + h) * 4096, vst + (q + 2) * 64, p, lane);
                    load_vq(sb + SM_VT + (bf * 2 + h) * 4096, vts + (q + 2) * 64, p, lane);
                    CP_COMMIT();
                }
            }
            // dot(M1, M2) over this warp's n-half, counted twice (ordered pairs)
            #pragma unroll
            for (int mf = 0; mf < 2; ++mf)
                #pragma unroll
                for (int nf = 0; nf < 4; ++nf) {
                    p4[mf * 2 + 0] += a1[mf][nf][0] * a2[mf][nf][0] +
                                      a1[mf][nf][1] * a2[mf][nf][1];
                    p4[mf * 2 + 1] += a1[mf][nf][2] * a2[mf][nf][2] +
                                      a1[mf][nf][3] * a2[mf][nf][3];
                }
            #pragma unroll
            for (int i = 0; i < 4; ++i) p4[i] *= 2.f;
        } else {
            // ---- diag unit ----
            // dks[k] = sum_l V_ss[l,k]^2 from global fp16 (same values the GEMM uses)
            {
                const __half* vp = g_vh + (size_t)((s * NFIELDS + s) * NL) * FDIM + tid;
                float a = 0.f;
                #pragma unroll 8
                for (int l = 0; l < NL; ++l) {
                    float f = __half2float(vp[(size_t)l * FDIM]);
                    a += f * f;
                }
                dks[tid] = a;
            }
            __syncthreads();

            load_vq(sb + SM_VS + h * 4096, vst, p, lane);
            CP_COMMIT();
            load_vq(sb + SM_VS + (2 + h) * 4096, vst + 64, p, lane);
            CP_COMMIT();
            load_xq_cvt(sb + SM_XS, xs, p, h, lane);
            load_xq_cvt(sb + SM_XS + 16384, xs + 64, p, h, lane);

            float dql[4] = {0.f, 0.f, 0.f, 0.f};
            const float* wp = w + s * FDIM;
            #pragma unroll
            for (int q = 0; q < 4; ++q) {
                if (q == 3) { CP_WAIT0(); } else { CP_WAIT1(); }
                __syncwarp();
                __syncthreads();                         // quarter visible (X pair + V halves)
                const int bf = q & 1;
                gemm32(sb + SM_XS + bf * 16384, sb + SM_VS + (bf * 2 + h) * 4096, p, lane, a1);
                // q + linear for this quarter (k-split by h, rows of own pair)
                {
                    const char* xsm = smem + SM_XS + bf * 16384;
                    const int kin0 = h * 32 + (lane & 3) * 8;
                    const int rb = p * 32 + (lane >> 2);
                    const float* dq = dks + q * 64;
                    const float* wq = wp + q * 64;
                    #pragma unroll
                    for (int i = 0; i < 8; ++i) {
                        int k = kin0 + i;
                        float dk = dq[k];
                        float wv = __ldg(wq + k);
                        #pragma unroll
                        for (int sl = 0; sl < 4; ++sl) {
                            float xv = __half2float(*(const __half*)(
                                xsm + SW128((rb + sl * 8) * 128 + k * 2)));
                            dql[sl] += xv * (4.f * wv - xv * dk);
                        }
                    }
                }
                BARX(bar_p, 64); BARX(bar_h, 128);       // pair done qlin/gemm, h done gemm
                if (q < 2) {
                    load_xq_cvt(sb + SM_XS + bf * 16384, xs + (q + 2) * 64, p, h, lane);
                    load_vq(sb + SM_VS + (bf * 2 + h) * 4096, vst + (q + 2) * 64, p, lane);
                    CP_COMMIT();
                }
            }
            // self dot - q + 4*linear
            #pragma unroll
            for (int mf = 0; mf < 2; ++mf)
                #pragma unroll
                for (int nf = 0; nf < 4; ++nf) {
                    p4[mf * 2 + 0] += a1[mf][nf][0] * a1[mf][nf][0] +
                                      a1[mf][nf][1] * a1[mf][nf][1];
                    p4[mf * 2 + 1] += a1[mf][nf][2] * a1[mf][nf][2] +
                                      a1[mf][nf][3] * a1[mf][nf][3];
                }
            #pragma unroll
            for (int i = 0; i < 4; ++i) p4[i] += dql[i];
        }

        // reduce over 4 lanes sharing each row; accumulate
        #pragma unroll
        for (int i = 0; i < 4; ++i) {
            p4[i] += __shfl_xor_sync(0xFFFFFFFFu, p4[i], 1);
            p4[i] += __shfl_xor_sync(0xFFFFFFFFu, p4[i], 2);
            acc_int[i] += p4[i];
        }
        // unit-end: free all buffers for next unit's prologue
        BARX(bar_p, 64); BARX(bar_h, 128);
    }

    if ((lane & 3) == 0) {
        #pragma unroll
        for (int sl = 0; sl < 4; ++sl) {
            int row = r0 + p * 32 + (lane >> 2) + sl * 8;
            atomicAdd(out + row, 0.25f * acc_int[sl]);
        }
    }
}

// ------------------------------------------------------------------
extern "C" void kernel_launch(void* const* d_in, const int* in_sizes, int n_in,
                              void* d_out, int out_size) {
    const float* x = (const float*)d_in[0];
    const float* b = (const float*)d_in[1];
    const float* w = (const float*)d_in[2];
    const float* V = (const float*)d_in[3];
    float* out = (float*)d_out;

    cudaFuncSetAttribute(ffm_main, cudaFuncAttributeMaxDynamicSharedMemorySize, SM_TOTAL);

    k_convert_v<<<(NFEAT * NFIELDS * NL + 255) / 256, 256>>>(V, b, out);
    ffm_main<<<dim3(NBATCH / ROWT, 9), NTHREADS, SM_TOTAL>>>(x, w, out);
}

// round 14
// speedup vs baseline: 1.6180x; 1.4208x over previous
#include <cuda_runtime.h>
#include <cuda_fp16.h>
#include <cstdint>

#define NFEAT   2048
#define NBATCH  8192
#define NFIELDS 8
#define FDIM    256
#define NL      64
#define ROWT    128
#define NTHREADS 256

// fp16 scratch (static device arrays -- no runtime allocation)
__device__ __half g_xh[(size_t)NBATCH * NFEAT];              // 32 MB, row-major [B, F]
__device__ __half g_vh[NFIELDS * NFIELDS * NL * FDIM];        // 2 MB, [s][t][l][k]

// ---------------- SMEM layout (97 KB -> 2 CTAs/SM) ----------------
// XS/XT: 2 k-quarter bufs x [128 rows x 128B] = 16 KB each buf
// VS/VT: 2 bufs x 2 h-halves x [32 l-rows x 128B] = 4 KB per (buf,h)
#define SM_DKS  0
#define SM_XS   1024
#define SM_XT   (SM_XS + 32768)
#define SM_VS   (SM_XT + 32768)
#define SM_VT   (SM_VS + 16384)
#define SM_TOTAL (SM_VT + 16384)   // 99328 B

#define SW128(off) ((off) ^ (((off) >> 3) & 0x70))

static __device__ __forceinline__ uint32_t smem_u32(const void* p) {
    uint32_t a;
    asm("{ .reg .u64 t; cvta.to.shared.u64 t, %1; cvt.u32.u64 %0, t; }" : "=r"(a) : "l"(p));
    return a;
}

#define CP_ASYNC16(dst, src) \
    asm volatile("cp.async.cg.shared.global [%0], [%1], 16;" :: "r"(dst), "l"(src))
#define CP_COMMIT() asm volatile("cp.async.commit_group;" ::: "memory")
#define CP_WAIT0()  asm volatile("cp.async.wait_group 0;" ::: "memory")
#define CP_WAIT1()  asm volatile("cp.async.wait_group 1;" ::: "memory")

// named barriers: 1+p (64 thr, pair scope), 5+h (128 thr, h-group scope)
#define BARX(id, cnt) asm volatile("bar.sync %0, %1;" :: "r"(id), "r"(cnt) : "memory")

static __device__ __forceinline__ void ldmx4(uint32_t addr, uint32_t& r0, uint32_t& r1,
                                             uint32_t& r2, uint32_t& r3) {
    asm volatile("ldmatrix.sync.aligned.m8n8.x4.shared.b16 {%0,%1,%2,%3}, [%4];"
                 : "=r"(r0), "=r"(r1), "=r"(r2), "=r"(r3) : "r"(addr));
}

static __device__ __forceinline__ void mma16816(float* d, uint32_t a0, uint32_t a1,
                                                uint32_t a2, uint32_t a3,
                                                uint32_t b0, uint32_t b1) {
    asm volatile(
        "mma.sync.aligned.m16n8k16.row.col.f32.f16.f16.f32 "
        "{%0,%1,%2,%3}, {%4,%5,%6,%7}, {%8,%9}, {%0,%1,%2,%3};"
        : "+f"(d[0]), "+f"(d[1]), "+f"(d[2]), "+f"(d[3])
        : "r"(a0), "r"(a1), "r"(a2), "r"(a3), "r"(b0), "r"(b1));
}

// Balanced unit groups: g0 = 4 pairs; g1..g8 = 3 pairs + 1 diag
__device__ const signed char U_S[36] = {
    0,0,0,0,  0,0,0,0,  1,1,1,1,  1,1,1,2,  2,2,2,3,  2,2,3,4,  3,3,3,5,  4,4,4,6,  5,5,6,7};
__device__ const signed char U_T[36] = {
    1,2,3,4,  5,6,7,0,  2,3,4,1,  5,6,7,2,  3,4,5,3,  6,7,4,4,  5,6,7,5,  5,6,7,6,  6,7,7,7};

// ------------------------------------------------------------------
// merged prepass: x -> fp16, V -> fp16 (transposed layout), out <- b
__global__ void k_prep(const float* __restrict__ x, const float* __restrict__ V,
                       const float* __restrict__ b, float* __restrict__ out) {
    size_t i = (size_t)blockIdx.x * blockDim.x + threadIdx.x;

    // x convert: 8 floats per thread (2M/8 = 262144 threads)
    size_t n8 = (size_t)NBATCH * NFEAT / 8;
    if (i < n8) {
        const float4* src = (const float4*)x;
        float4 f0 = src[2 * i], f1 = src[2 * i + 1];
        __half2 h0 = __floats2half2_rn(f0.x, f0.y);
        __half2 h1 = __floats2half2_rn(f0.z, f0.w);
        __half2 h2 = __floats2half2_rn(f1.x, f1.y);
        __half2 h3 = __floats2half2_rn(f1.z, f1.w);
        uint4 o;
        o.x = *(uint32_t*)&h0; o.y = *(uint32_t*)&h1;
        o.z = *(uint32_t*)&h2; o.w = *(uint32_t*)&h3;
        ((uint4*)g_xh)[i] = o;
    }
    // V convert + transpose: [F][t][l] -> g_vh[s][t][l][k]
    if (i < (size_t)(NFEAT * NFIELDS * NL)) {
        int idx = (int)i;
        int f = idx / (NFIELDS * NL);
        int rest = idx % (NFIELDS * NL);
        int t = rest / NL, l = rest % NL;
        int s = f >> 8, k = f & 255;
        g_vh[(((s * NFIELDS + t) * NL) + l) * FDIM + k] = __float2half_rn(V[idx]);
    }
    // out init
    if (i < NBATCH) out[i] = b[0];
}

// ------------------------------------------------------------------
// X quarter slice for this thread's pair: rows p*32+h*16..+16 x 128B; 4 x 16B per thread
static __device__ __forceinline__ void load_xq(uint32_t sbuf, const __half* gsrc,
                                               int p, int h, int lane) {
    #pragma unroll
    for (int it = 0; it < 4; ++it) {
        int tsk = lane + it * 32;                 // 0..127
        int row = p * 32 + h * 16 + (tsk >> 3);
        int c = tsk & 7;
        uint32_t sa = sbuf + SW128(row * 128 + c * 16);
        const char* ga = (const char*)gsrc + (size_t)row * (NFEAT * 2) + c * 16;
        CP_ASYNC16(sa, ga);
    }
}

// V half-quarter for this h-group: 32 l-rows x 128B; 2 x 16B per thread
// gsrc pre-offset to [l = h*32][k = q*64]
static __device__ __forceinline__ void load_vq(uint32_t sbuf, const __half* gsrc,
                                               int p, int lane) {
    #pragma unroll
    for (int it = 0; it < 2; ++it) {
        int tsk = p * 32 + lane + it * 128;       // 0..255, disjoint across h-group
        int row = tsk >> 3;
        int c = tsk & 7;
        uint32_t sa = sbuf + SW128(row * 128 + c * 16);
        const char* ga = (const char*)gsrc + (size_t)row * (FDIM * 2) + c * 16;
        CP_ASYNC16(sa, ga);
    }
}

// Quarter GEMM: acc += X_q(warp's 32 rows x 64k) @ V_halfq^T   (m32 x n32 x k64)
static __device__ __forceinline__ void gemm32(uint32_t sx, uint32_t sv,
                                              int p, int lane, float acc[2][4][4]) {
    const int arow = p * 32 + (lane & 15);
    const int ak = ((lane >> 4) << 3) * 2;
    const int brow = ((lane >> 4) << 3) + (lane & 7);
    const int bk = (((lane >> 3) & 1) << 3) * 2;
    #pragma unroll
    for (int k4 = 0; k4 < 4; ++k4) {
        const int kb = k4 * 32;
        uint32_t a00, a01, a02, a03, a10, a11, a12, a13;
        ldmx4(sx + SW128(arow * 128 + kb + ak), a00, a01, a02, a03);
        ldmx4(sx + SW128((arow + 16) * 128 + kb + ak), a10, a11, a12, a13);
        #pragma unroll
        for (int vt = 0; vt < 2; ++vt) {
            uint32_t b0, b1, b2, b3;
            ldmx4(sv + SW128((vt * 16 + brow) * 128 + kb + bk), b0, b1, b2, b3);
            mma16816(acc[0][2 * vt],     a00, a01, a02, a03, b0, b1);
            mma16816(acc[0][2 * vt + 1], a00, a01, a02, a03, b2, b3);
            mma16816(acc[1][2 * vt],     a10, a11, a12, a13, b0, b1);
            mma16816(acc[1][2 * vt + 1], a10, a11, a12, a13, b2, b3);
        }
    }
}

static __device__ __forceinline__ void zero4(float acc[2][4][4]) {
    #pragma unroll
    for (int m = 0; m < 2; ++m)
        #pragma unroll
        for (int n = 0; n < 4; ++n)
            #pragma unroll
            for (int j = 0; j < 4; ++j) acc[m][n][j] = 0.f;
}

__global__ __launch_bounds__(NTHREADS, 2)
void ffm_main(const float* __restrict__ w, float* __restrict__ out) {
    extern __shared__ char smem[];
    const uint32_t sb = smem_u32(smem);
    const int tid = threadIdx.x;
    const int wrp = tid >> 5;
    const int lane = tid & 31;
    const int p = wrp >> 1;          // pair (m-tile) 0..3
    const int h = wrp & 1;           // n-half 0..1
    const int r0 = blockIdx.x * ROWT;
    float* dks = (float*)(smem + SM_DKS);

    const int bar_p = 1 + p, bar_h = 5 + h;

    float acc_int[4] = {0.f, 0.f, 0.f, 0.f};   // row = p*32 + (lane>>2) + slot*8

    for (int uu = 0; uu < 4; ++uu) {
        const int u = blockIdx.y * 4 + uu;
        const int s = U_S[u], t = U_T[u];
        const __half* xs = g_xh + (size_t)r0 * NFEAT + s * FDIM;
        const __half* xt = g_xh + (size_t)r0 * NFEAT + t * FDIM;
        const __half* vst = g_vh + (size_t)((s * NFIELDS + t) * NL + h * 32) * FDIM;
        const __half* vts = g_vh + (size_t)((t * NFIELDS + s) * NL + h * 32) * FDIM;

        float a1[2][4][4];
        zero4(a1);
        float p4[4] = {0.f, 0.f, 0.f, 0.f};

        if (s != t) {
            float a2[2][4][4];
            zero4(a2);
            // prologue: quarters 0,1
            #pragma unroll
            for (int q = 0; q < 2; ++q) {
                load_xq(sb + SM_XS + q * 16384, xs + q * 64, p, h, lane);
                load_xq(sb + SM_XT + q * 16384, xt + q * 64, p, h, lane);
                load_vq(sb + SM_VS + (q * 2 + h) * 4096, vst + q * 64, p, lane);
                load_vq(sb + SM_VT + (q * 2 + h) * 4096, vts + q * 64, p, lane);
                CP_COMMIT();
            }
            #pragma unroll
            for (int q = 0; q < 4; ++q) {
                if (q == 3) { CP_WAIT0(); } else { CP_WAIT1(); }
                __syncwarp();
                BARX(bar_p, 64); BARX(bar_h, 128);      // quarter q visible everywhere
                const int bf = q & 1;
                gemm32(sb + SM_XS + bf * 16384, sb + SM_VS + (bf * 2 + h) * 4096, p, lane, a1);
                gemm32(sb + SM_XT + bf * 16384, sb + SM_VT + (bf * 2 + h) * 4096, p, lane, a2);
                if (q < 2) {
                    BARX(bar_p, 64); BARX(bar_h, 128);  // co-owners done reading buf
                    load_xq(sb + SM_XS + bf * 16384, xs + (q + 2) * 64, p, h, lane);
                    load_xq(sb + SM_XT + bf * 16384, xt + (q + 2) * 64, p, h, lane);
                    load_vq(sb + SM_VS + (bf * 2 + h) * 4096, vst + (q + 2) * 64, p, lane);
                    load_vq(sb + SM_VT + (bf * 2 + h) * 4096, vts + (q + 2) * 64, p, lane);
                    CP_COMMIT();
                }
            }
            // dot(M1, M2) over this warp's n-half, counted twice (ordered pairs)
            #pragma unroll
            for (int mf = 0; mf < 2; ++mf)
                #pragma unroll
                for (int nf = 0; nf < 4; ++nf) {
                    p4[mf * 2 + 0] += a1[mf][nf][0] * a2[mf][nf][0] +
                                      a1[mf][nf][1] * a2[mf][nf][1];
                    p4[mf * 2 + 1] += a1[mf][nf][2] * a2[mf][nf][2] +
                                      a1[mf][nf][3] * a2[mf][nf][3];
                }
            #pragma unroll
            for (int i = 0; i < 4; ++i) p4[i] *= 2.f;
        } else {
            // ---- diag unit ----
            // dks[k] = sum_l V_ss[l,k]^2 from global fp16 (same values the GEMM uses)
            {
                const __half* vp = g_vh + (size_t)((s * NFIELDS + s) * NL) * FDIM + tid;
                float a = 0.f;
                #pragma unroll 8
                for (int l = 0; l < NL; ++l) {
                    float f = __half2float(vp[(size_t)l * FDIM]);
                    a += f * f;
                }
                dks[tid] = a;
            }
            __syncthreads();

            #pragma unroll
            for (int q = 0; q < 2; ++q) {
                load_xq(sb + SM_XS + q * 16384, xs + q * 64, p, h, lane);
                load_vq(sb + SM_VS + (q * 2 + h) * 4096, vst + q * 64, p, lane);
                CP_COMMIT();
            }
            float dql[4] = {0.f, 0.f, 0.f, 0.f};
            const float* wp = w + s * FDIM;
            #pragma unroll
            for (int q = 0; q < 4; ++q) {
                if (q == 3) { CP_WAIT0(); } else { CP_WAIT1(); }
                __syncwarp();
                __syncthreads();                         // quarter visible (X pair + V halves)
                const int bf = q & 1;
                gemm32(sb + SM_XS + bf * 16384, sb + SM_VS + (bf * 2 + h) * 4096, p, lane, a1);
                // q + linear for this quarter (k-split by h, rows of own pair)
                {
                    const char* xsm = smem + SM_XS + bf * 16384;
                    const int kin0 = h * 32 + (lane & 3) * 8;
                    const int rb = p * 32 + (lane >> 2);
                    const float* dq = dks + q * 64;
                    const float* wq = wp + q * 64;
                    #pragma unroll
                    for (int i = 0; i < 8; ++i) {
                        int k = kin0 + i;
                        float dk = dq[k];
                        float wv = __ldg(wq + k);
                        #pragma unroll
                        for (int sl = 0; sl < 4; ++sl) {
                            float xv = __half2float(*(const __half*)(
                                xsm + SW128((rb + sl * 8) * 128 + k * 2)));
                            dql[sl] += xv * (4.f * wv - xv * dk);
                        }
                    }
                }
                BARX(bar_p, 64); BARX(bar_h, 128);       // pair done qlin/gemm, h done gemm
                if (q < 2) {
                    load_xq(sb + SM_XS + bf * 16384, xs + (q + 2) * 64, p, h, lane);
                    load_vq(sb + SM_VS + (bf * 2 + h) * 4096, vst + (q + 2) * 64, p, lane);
                    CP_COMMIT();
                }
            }
            // self dot - q + 4*linear
            #pragma unroll
            for (int mf = 0; mf < 2; ++mf)
                #pragma unroll
                for (int nf = 0; nf < 4; ++nf) {
                    p4[mf * 2 + 0] += a1[mf][nf][0] * a1[mf][nf][0] +
                                      a1[mf][nf][1] * a1[mf][nf][1];
                    p4[mf * 2 + 1] += a1[mf][nf][2] * a1[mf][nf][2] +
                                      a1[mf][nf][3] * a1[mf][nf][3];
                }
            #pragma unroll
            for (int i = 0; i < 4; ++i) p4[i] += dql[i];
        }

        // reduce over 4 lanes sharing each row; accumulate
        #pragma unroll
        for (int i = 0; i < 4; ++i) {
            p4[i] += __shfl_xor_sync(0xFFFFFFFFu, p4[i], 1);
            p4[i] += __shfl_xor_sync(0xFFFFFFFFu, p4[i], 2);
            acc_int[i] += p4[i];
        }
        // unit-end: free all buffers for next unit's prologue
        BARX(bar_p, 64); BARX(bar_h, 128);
    }

    if ((lane & 3) == 0) {
        #pragma unroll
        for (int sl = 0; sl < 4; ++sl) {
            int row = r0 + p * 32 + (lane >> 2) + sl * 8;
            atomicAdd(out + row, 0.25f * acc_int[sl]);
        }
    }
}

// ------------------------------------------------------------------
extern "C" void kernel_launch(void* const* d_in, const int* in_sizes, int n_in,
                              void* d_out, int out_size) {
    const float* x = (const float*)d_in[0];
    const float* b = (const float*)d_in[1];
    const float* w = (const float*)d_in[2];
    const float* V = (const float*)d_in[3];
    float* out = (float*)d_out;

    cudaFuncSetAttribute(ffm_main, cudaFuncAttributeMaxDynamicSharedMemorySize, SM_TOTAL);

    {
        size_t n8 = (size_t)NBATCH * NFEAT / 8;   // largest of the three prep workloads
        k_prep<<<(unsigned)((n8 + 255) / 256), 256>>>(x, V, b, out);
    }
    ffm_main<<<dim3(NBATCH / ROWT, 9), NTHREADS, SM_TOTAL>>>(w, out);
}

// round 15
// speedup vs baseline: 1.6317x; 1.0085x over previous
#include <cuda_runtime.h>
#include <cuda_fp16.h>
#include <cstdint>

#define NFEAT   2048
#define NBATCH  8192
#define NFIELDS 8
#define FDIM    256
#define NL      64
#define ROWT    128
#define NTHREADS 256

// fp16 scratch (static device arrays -- no runtime allocation)
__device__ __half g_xh[(size_t)NBATCH * NFEAT];              // 32 MB, row-major [B, F]
__device__ __half g_vh[NFIELDS * NFIELDS * NL * FDIM];        // 2 MB, [s][t][l][k]

// ---------------- SMEM layout (97 KB -> 2 CTAs/SM) ----------------
#define SM_DKS  0
#define SM_XS   1024
#define SM_XT   (SM_XS + 32768)
#define SM_VS   (SM_XT + 32768)
#define SM_VT   (SM_VS + 16384)
#define SM_TOTAL (SM_VT + 16384)   // 99328 B

#define SW128(off) ((off) ^ (((off) >> 3) & 0x70))

static __device__ __forceinline__ uint32_t smem_u32(const void* p) {
    uint32_t a;
    asm("{ .reg .u64 t; cvta.to.shared.u64 t, %1; cvt.u32.u64 %0, t; }" : "=r"(a) : "l"(p));
    return a;
}

#define CP_ASYNC16(dst, src) \
    asm volatile("cp.async.cg.shared.global [%0], [%1], 16;" :: "r"(dst), "l"(src))
#define CP_COMMIT() asm volatile("cp.async.commit_group;" ::: "memory")
#define CP_WAIT0()  asm volatile("cp.async.wait_group 0;" ::: "memory")
#define CP_WAIT1()  asm volatile("cp.async.wait_group 1;" ::: "memory")

// named barriers: 1+p (64 thr, pair scope), 5+h (128 thr, h-group scope)
#define BARX(id, cnt) asm volatile("bar.sync %0, %1;" :: "r"(id), "r"(cnt) : "memory")

static __device__ __forceinline__ void ldmx4(uint32_t addr, uint32_t& r0, uint32_t& r1,
                                             uint32_t& r2, uint32_t& r3) {
    asm volatile("ldmatrix.sync.aligned.m8n8.x4.shared.b16 {%0,%1,%2,%3}, [%4];"
                 : "=r"(r0), "=r"(r1), "=r"(r2), "=r"(r3) : "r"(addr));
}

static __device__ __forceinline__ void mma16816(float* d, uint32_t a0, uint32_t a1,
                                                uint32_t a2, uint32_t a3,
                                                uint32_t b0, uint32_t b1) {
    asm volatile(
        "mma.sync.aligned.m16n8k16.row.col.f32.f16.f16.f32 "
        "{%0,%1,%2,%3}, {%4,%5,%6,%7}, {%8,%9}, {%0,%1,%2,%3};"
        : "+f"(d[0]), "+f"(d[1]), "+f"(d[2]), "+f"(d[3])
        : "r"(a0), "r"(a1), "r"(a2), "r"(a3), "r"(b0), "r"(b1));
}

// Balanced unit groups: g0 = 4 pairs; g1..g8 = 3 pairs + 1 diag (diag ALWAYS at uu==3)
__device__ const signed char U_S[36] = {
    0,0,0,0,  0,0,0,0,  1,1,1,1,  1,1,1,2,  2,2,2,3,  2,2,3,4,  3,3,3,5,  4,4,4,6,  5,5,6,7};
__device__ const signed char U_T[36] = {
    1,2,3,4,  5,6,7,0,  2,3,4,1,  5,6,7,2,  3,4,5,3,  6,7,4,4,  5,6,7,5,  5,6,7,6,  6,7,7,7};

// ------------------------------------------------------------------
// merged prepass: x -> fp16 (16 floats/thread), V -> fp16 transposed, out <- b
__global__ void k_prep(const float* __restrict__ x, const float* __restrict__ V,
                       const float* __restrict__ b, float* __restrict__ out) {
    size_t i = (size_t)blockIdx.x * blockDim.x + threadIdx.x;   // 1048576 threads

    // x convert: 16 floats -> 2 uint4 stores
    size_t n16 = (size_t)NBATCH * NFEAT / 16;
    if (i < n16) {
        const float4* src = (const float4*)x + 4 * i;
        uint4* dst = (uint4*)g_xh + 2 * i;
        #pragma unroll
        for (int j = 0; j < 2; ++j) {
            float4 f0 = src[2 * j], f1 = src[2 * j + 1];
            __half2 h0 = __floats2half2_rn(f0.x, f0.y);
            __half2 h1 = __floats2half2_rn(f0.z, f0.w);
            __half2 h2 = __floats2half2_rn(f1.x, f1.y);
            __half2 h3 = __floats2half2_rn(f1.z, f1.w);
            uint4 o;
            o.x = *(uint32_t*)&h0; o.y = *(uint32_t*)&h1;
            o.z = *(uint32_t*)&h2; o.w = *(uint32_t*)&h3;
            dst[j] = o;
        }
    }
    // V convert + transpose: [F][t][l] -> g_vh[s][t][l][k]   (exactly 1048576 elements)
    if (i < (size_t)(NFEAT * NFIELDS * NL)) {
        int idx = (int)i;
        int f = idx / (NFIELDS * NL);
        int rest = idx % (NFIELDS * NL);
        int t = rest / NL, l = rest % NL;
        int s = f >> 8, k = f & 255;
        g_vh[(((s * NFIELDS + t) * NL) + l) * FDIM + k] = __float2half_rn(V[idx]);
    }
    if (i < NBATCH) out[i] = b[0];
}

// ------------------------------------------------------------------
// X quarter slice for this thread's pair: rows p*32+h*16..+16 x 128B; 4 x 16B per thread
static __device__ __forceinline__ void load_xq(uint32_t sbuf, const __half* gsrc,
                                               int p, int h, int lane) {
    #pragma unroll
    for (int it = 0; it < 4; ++it) {
        int tsk = lane + it * 32;                 // 0..127
        int row = p * 32 + h * 16 + (tsk >> 3);
        int c = tsk & 7;
        uint32_t sa = sbuf + SW128(row * 128 + c * 16);
        const char* ga = (const char*)gsrc + (size_t)row * (NFEAT * 2) + c * 16;
        CP_ASYNC16(sa, ga);
    }
}

// V half-quarter for this h-group: 32 l-rows x 128B; 2 x 16B per thread
static __device__ __forceinline__ void load_vq(uint32_t sbuf, const __half* gsrc,
                                               int p, int lane) {
    #pragma unroll
    for (int it = 0; it < 2; ++it) {
        int tsk = p * 32 + lane + it * 128;       // 0..255, disjoint across h-group
        int row = tsk >> 3;
        int c = tsk & 7;
        uint32_t sa = sbuf + SW128(row * 128 + c * 16);
        const char* ga = (const char*)gsrc + (size_t)row * (FDIM * 2) + c * 16;
        CP_ASYNC16(sa, ga);
    }
}

// issue all cp.asyncs for pipeline stage (u2, q2) + one commit.
// Pair units load XS/XT/VS/VT; diag units only XS/VS.
static __device__ __forceinline__ void issue_stage(uint32_t sb, int r0, int p, int h,
                                                   int lane, int u2, int q2) {
    const int s2 = U_S[u2], t2 = U_T[u2];
    const int bf = q2 & 1;
    load_xq(sb + SM_XS + bf * 16384,
            g_xh + (size_t)r0 * NFEAT + s2 * FDIM + q2 * 64, p, h, lane);
    load_vq(sb + SM_VS + (bf * 2 + h) * 4096,
            g_vh + (size_t)((s2 * NFIELDS + t2) * NL + h * 32) * FDIM + q2 * 64, p, lane);
    if (s2 != t2) {
        load_xq(sb + SM_XT + bf * 16384,
                g_xh + (size_t)r0 * NFEAT + t2 * FDIM + q2 * 64, p, h, lane);
        load_vq(sb + SM_VT + (bf * 2 + h) * 4096,
                g_vh + (size_t)((t2 * NFIELDS + s2) * NL + h * 32) * FDIM + q2 * 64, p, lane);
    }
    CP_COMMIT();
}

// Quarter GEMM: acc += X_q(warp's 32 rows x 64k) @ V_halfq^T   (m32 x n32 x k64)
static __device__ __forceinline__ void gemm32(uint32_t sx, uint32_t sv,
                                              int p, int lane, float acc[2][4][4]) {
    const int arow = p * 32 + (lane & 15);
    const int ak = ((lane >> 4) << 3) * 2;
    const int brow = ((lane >> 4) << 3) + (lane & 7);
    const int bk = (((lane >> 3) & 1) << 3) * 2;
    #pragma unroll
    for (int k4 = 0; k4 < 4; ++k4) {
        const int kb = k4 * 32;
        uint32_t a00, a01, a02, a03, a10, a11, a12, a13;
        ldmx4(sx + SW128(arow * 128 + kb + ak), a00, a01, a02, a03);
        ldmx4(sx + SW128((arow + 16) * 128 + kb + ak), a10, a11, a12, a13);
        #pragma unroll
        for (int vt = 0; vt < 2; ++vt) {
            uint32_t b0, b1, b2, b3;
            ldmx4(sv + SW128((vt * 16 + brow) * 128 + kb + bk), b0, b1, b2, b3);
            mma16816(acc[0][2 * vt],     a00, a01, a02, a03, b0, b1);
            mma16816(acc[0][2 * vt + 1], a00, a01, a02, a03, b2, b3);
            mma16816(acc[1][2 * vt],     a10, a11, a12, a13, b0, b1);
            mma16816(acc[1][2 * vt + 1], a10, a11, a12, a13, b2, b3);
        }
    }
}

static __device__ __forceinline__ void zero4(float acc[2][4][4]) {
    #pragma unroll
    for (int m = 0; m < 2; ++m)
        #pragma unroll
        for (int n = 0; n < 4; ++n)
            #pragma unroll
            for (int j = 0; j < 4; ++j) acc[m][n][j] = 0.f;
}

__global__ __launch_bounds__(NTHREADS, 2)
void ffm_main(const float* __restrict__ w, float* __restrict__ out) {
    extern __shared__ char smem[];
    const uint32_t sb = smem_u32(smem);
    const int tid = threadIdx.x;
    const int wrp = tid >> 5;
    const int lane = tid & 31;
    const int p = wrp >> 1;          // pair (m-tile) 0..3
    const int h = wrp & 1;           // n-half 0..1
    const int r0 = blockIdx.x * ROWT;
    const int u0 = blockIdx.y * 4;
    float* dks = (float*)(smem + SM_DKS);

    const int bar_p = 1 + p, bar_h = 5 + h;

    // pipeline prologue: stages (u0,0), (u0,1)
    issue_stage(sb, r0, p, h, lane, u0, 0);
    issue_stage(sb, r0, p, h, lane, u0, 1);

    // dks for this group's diag unit (always at uu==3 when present) -- overlaps prologue
    {
        const int ud = u0 + 3;
        const int sd = U_S[ud];
        if (sd == U_T[ud]) {
            const __half* vp = g_vh + (size_t)((sd * NFIELDS + sd) * NL) * FDIM + tid;
            float a = 0.f;
            #pragma unroll 8
            for (int l = 0; l < NL; ++l) {
                float f = __half2float(vp[(size_t)l * FDIM]);
                a += f * f;
            }
            dks[tid] = a;
        }
    }
    __syncthreads();   // dks visible for the whole kernel

    float acc_int[4] = {0.f, 0.f, 0.f, 0.f};   // row = p*32 + (lane>>2) + slot*8

    for (int uu = 0; uu < 4; ++uu) {
        const int u = u0 + uu;
        const int s = U_S[u], t = U_T[u];

        float a1[2][4][4];
        zero4(a1);
        float p4[4] = {0.f, 0.f, 0.f, 0.f};

        if (s != t) {
            float a2[2][4][4];
            zero4(a2);
            #pragma unroll
            for (int q = 0; q < 4; ++q) {
                if (uu == 3 && q == 3) { CP_WAIT0(); } else { CP_WAIT1(); }
                BARX(bar_p, 64); BARX(bar_h, 128);      // stage (uu,q) visible
                const int bf = q & 1;
                gemm32(sb + SM_XS + bf * 16384, sb + SM_VS + (bf * 2 + h) * 4096, p, lane, a1);
                gemm32(sb + SM_XT + bf * 16384, sb + SM_VT + (bf * 2 + h) * 4096, p, lane, a2);
                // prefetch stage (uu,q)+2 (crossing unit boundary when q>=2)
                int nq = q + 2, nu = uu;
                if (nq >= 4) { nq -= 4; ++nu; }
                if (nu < 4) {
                    BARX(bar_p, 64); BARX(bar_h, 128);  // buffer bf free
                    issue_stage(sb, r0, p, h, lane, u0 + nu, nq);
                }
            }
            // dot(M1, M2), counted twice (ordered pairs)
            #pragma unroll
            for (int mf = 0; mf < 2; ++mf)
                #pragma unroll
                for (int nf = 0; nf < 4; ++nf) {
                    p4[mf * 2 + 0] += a1[mf][nf][0] * a2[mf][nf][0] +
                                      a1[mf][nf][1] * a2[mf][nf][1];
                    p4[mf * 2 + 1] += a1[mf][nf][2] * a2[mf][nf][2] +
                                      a1[mf][nf][3] * a2[mf][nf][3];
                }
            #pragma unroll
            for (int i = 0; i < 4; ++i) p4[i] *= 2.f;
        } else {
            // diag unit (uu==3): gemm + q/linear per quarter; dks precomputed
            float dql[4] = {0.f, 0.f, 0.f, 0.f};
            const float* wp = w + s * FDIM;
            #pragma unroll
            for (int q = 0; q < 4; ++q) {
                if (uu == 3 && q == 3) { CP_WAIT0(); } else { CP_WAIT1(); }
                BARX(bar_p, 64); BARX(bar_h, 128);
                const int bf = q & 1;
                gemm32(sb + SM_XS + bf * 16384, sb + SM_VS + (bf * 2 + h) * 4096, p, lane, a1);
                {
                    const char* xsm = smem + SM_XS + bf * 16384;
                    const int kin0 = h * 32 + (lane & 3) * 8;
                    const int rb = p * 32 + (lane >> 2);
                    const float* dq = dks + q * 64;
                    const float* wq = wp + q * 64;
                    #pragma unroll
                    for (int i = 0; i < 8; ++i) {
                        int k = kin0 + i;
                        float dk = dq[k];
                        float wv = __ldg(wq + k);
                        #pragma unroll
                        for (int sl = 0; sl < 4; ++sl) {
                            float xv = __half2float(*(const __half*)(
                                xsm + SW128((rb + sl * 8) * 128 + k * 2)));
                            dql[sl] += xv * (4.f * wv - xv * dk);
                        }
                    }
                }
                int nq = q + 2, nu = uu;
                if (nq >= 4) { nq -= 4; ++nu; }
                if (nu < 4) {
                    BARX(bar_p, 64); BARX(bar_h, 128);
                    issue_stage(sb, r0, p, h, lane, u0 + nu, nq);
                }
            }
            // self dot - q + 4*linear
            #pragma unroll
            for (int mf = 0; mf < 2; ++mf)
                #pragma unroll
                for (int nf = 0; nf < 4; ++nf) {
                    p4[mf * 2 + 0] += a1[mf][nf][0] * a1[mf][nf][0] +
                                      a1[mf][nf][1] * a1[mf][nf][1];
                    p4[mf * 2 + 1] += a1[mf][nf][2] * a1[mf][nf][2] +
                                      a1[mf][nf][3] * a1[mf][nf][3];
                }
            #pragma unroll
            for (int i = 0; i < 4; ++i) p4[i] += dql[i];
        }

        // reduce over 4 lanes sharing each row; accumulate
        #pragma unroll
        for (int i = 0; i < 4; ++i) {
            p4[i] += __shfl_xor_sync(0xFFFFFFFFu, p4[i], 1);
            p4[i] += __shfl_xor_sync(0xFFFFFFFFu, p4[i], 2);
            acc_int[i] += p4[i];
        }
    }

    if ((lane & 3) == 0) {
        #pragma unroll
        for (int sl = 0; sl < 4; ++sl) {
            int row = r0 + p * 32 + (lane >> 2) + sl * 8;
            atomicAdd(out + row, 0.25f * acc_int[sl]);
        }
    }
}

// ------------------------------------------------------------------
extern "C" void kernel_launch(void* const* d_in, const int* in_sizes, int n_in,
                              void* d_out, int out_size) {
    const float* x = (const float*)d_in[0];
    const float* b = (const float*)d_in[1];
    const float* w = (const float*)d_in[2];
    const float* V = (const float*)d_in[3];
    float* out = (float*)d_out;

    cudaFuncSetAttribute(ffm_main, cudaFuncAttributeMaxDynamicSharedMemorySize, SM_TOTAL);

    {
        size_t n16 = (size_t)NBATCH * NFEAT / 16;   // 1048576 threads cover x, V, out
        k_prep<<<(unsigned)((n16 + 255) / 256), 256>>>(x, V, b, out);
    }
    ffm_main<<<dim3(NBATCH / ROWT, 9), NTHREADS, SM_TOTAL>>>(w, out);
}

// round 16
// speedup vs baseline: 1.7000x; 1.0418x over previous
#include <cuda_runtime.h>
#include <cuda_fp16.h>
#include <cstdint>

#define NFEAT   2048
#define NBATCH  8192
#define NFIELDS 8
#define FDIM    256
#define NL      64
#define ROWT    128
#define NTHREADS 256

// fp16 scratch (static device arrays -- no runtime allocation)
__device__ __half g_xh[(size_t)NBATCH * NFEAT];              // 32 MB, row-major [B, F]
__device__ __half g_vh[NFIELDS * NFIELDS * NL * FDIM];        // 2 MB, [s][t][l][k]

// ---------------- SMEM layout (97 KB -> 2 CTAs/SM) ----------------
#define SM_DKS  0
#define SM_XS   1024
#define SM_XT   (SM_XS + 32768)
#define SM_VS   (SM_XT + 32768)
#define SM_VT   (SM_VS + 16384)
#define SM_TOTAL (SM_VT + 16384)   // 99328 B

#define SW128(off) ((off) ^ (((off) >> 3) & 0x70))

static __device__ __forceinline__ uint32_t smem_u32(const void* p) {
    uint32_t a;
    asm("{ .reg .u64 t; cvta.to.shared.u64 t, %1; cvt.u32.u64 %0, t; }" : "=r"(a) : "l"(p));
    return a;
}

#define CP_ASYNC16(dst, src) \
    asm volatile("cp.async.cg.shared.global [%0], [%1], 16;" :: "r"(dst), "l"(src))
#define CP_COMMIT() asm volatile("cp.async.commit_group;" ::: "memory")
#define CP_WAIT0()  asm volatile("cp.async.wait_group 0;" ::: "memory")

// named barriers: 1+p (64 thr, pair scope), 5+h (128 thr, h-group scope)
#define BARX(id, cnt) asm volatile("bar.sync %0, %1;" :: "r"(id), "r"(cnt) : "memory")

static __device__ __forceinline__ void ldmx4(uint32_t addr, uint32_t& r0, uint32_t& r1,
                                             uint32_t& r2, uint32_t& r3) {
    asm volatile("ldmatrix.sync.aligned.m8n8.x4.shared.b16 {%0,%1,%2,%3}, [%4];"
                 : "=r"(r0), "=r"(r1), "=r"(r2), "=r"(r3) : "r"(addr));
}

static __device__ __forceinline__ void mma16816(float* d, uint32_t a0, uint32_t a1,
                                                uint32_t a2, uint32_t a3,
                                                uint32_t b0, uint32_t b1) {
    asm volatile(
        "mma.sync.aligned.m16n8k16.row.col.f32.f16.f16.f32 "
        "{%0,%1,%2,%3}, {%4,%5,%6,%7}, {%8,%9}, {%0,%1,%2,%3};"
        : "+f"(d[0]), "+f"(d[1]), "+f"(d[2]), "+f"(d[3])
        : "r"(a0), "r"(a1), "r"(a2), "r"(a3), "r"(b0), "r"(b1));
}

// Balanced unit groups: g0 = 4 pairs; g1..g8 = 3 pairs + 1 diag (diag ALWAYS at uu==3)
__device__ const signed char U_S[36] = {
    0,0,0,0,  0,0,0,0,  1,1,1,1,  1,1,1,2,  2,2,2,3,  2,2,3,4,  3,3,3,5,  4,4,4,6,  5,5,6,7};
__device__ const signed char U_T[36] = {
    1,2,3,4,  5,6,7,0,  2,3,4,1,  5,6,7,2,  3,4,5,3,  6,7,4,4,  5,6,7,5,  5,6,7,6,  6,7,7,7};

// ------------------------------------------------------------------
// merged prepass: x -> fp16 (16 floats/thread), V -> fp16 transposed, out <- b
__global__ void k_prep(const float* __restrict__ x, const float* __restrict__ V,
                       const float* __restrict__ b, float* __restrict__ out) {
    size_t i = (size_t)blockIdx.x * blockDim.x + threadIdx.x;   // 1048576 threads

    size_t n16 = (size_t)NBATCH * NFEAT / 16;
    if (i < n16) {
        const float4* src = (const float4*)x + 4 * i;
        uint4* dst = (uint4*)g_xh + 2 * i;
        #pragma unroll
        for (int j = 0; j < 2; ++j) {
            float4 f0 = src[2 * j], f1 = src[2 * j + 1];
            __half2 h0 = __floats2half2_rn(f0.x, f0.y);
            __half2 h1 = __floats2half2_rn(f0.z, f0.w);
            __half2 h2 = __floats2half2_rn(f1.x, f1.y);
            __half2 h3 = __floats2half2_rn(f1.z, f1.w);
            uint4 o;
            o.x = *(uint32_t*)&h0; o.y = *(uint32_t*)&h1;
            o.z = *(uint32_t*)&h2; o.w = *(uint32_t*)&h3;
            dst[j] = o;
        }
    }
    if (i < (size_t)(NFEAT * NFIELDS * NL)) {
        int idx = (int)i;
        int f = idx / (NFIELDS * NL);
        int rest = idx % (NFIELDS * NL);
        int t = rest / NL, l = rest % NL;
        int s = f >> 8, k = f & 255;
        g_vh[(((s * NFIELDS + t) * NL) + l) * FDIM + k] = __float2half_rn(V[idx]);
    }
    if (i < NBATCH) out[i] = b[0];
}

// ------------------------------------------------------------------
// X quarter slice for this thread's pair: rows p*32+h*16..+16 x 128B; 4 x 16B per thread
static __device__ __forceinline__ void load_xq(uint32_t sbuf, const __half* gsrc,
                                               int p, int h, int lane) {
    #pragma unroll
    for (int it = 0; it < 4; ++it) {
        int tsk = lane + it * 32;                 // 0..127
        int row = p * 32 + h * 16 + (tsk >> 3);
        int c = tsk & 7;
        uint32_t sa = sbuf + SW128(row * 128 + c * 16);
        const char* ga = (const char*)gsrc + (size_t)row * (NFEAT * 2) + c * 16;
        CP_ASYNC16(sa, ga);
    }
}

// V half-quarter for this h-group: 32 l-rows x 128B; 2 x 16B per thread
static __device__ __forceinline__ void load_vq(uint32_t sbuf, const __half* gsrc,
                                               int p, int lane) {
    #pragma unroll
    for (int it = 0; it < 2; ++it) {
        int tsk = p * 32 + lane + it * 128;       // 0..255, disjoint across h-group
        int row = tsk >> 3;
        int c = tsk & 7;
        uint32_t sa = sbuf + SW128(row * 128 + c * 16);
        const char* ga = (const char*)gsrc + (size_t)row * (FDIM * 2) + c * 16;
        CP_ASYNC16(sa, ga);
    }
}

// issue all cp.asyncs for global pipeline stage g = u*4+q within this y-group, + commit.
static __device__ __forceinline__ void issue_stage(uint32_t sb, int r0, int p, int h,
                                                   int lane, int u0, int g) {
    const int u2 = u0 + (g >> 2), q2 = g & 3;
    const int s2 = U_S[u2], t2 = U_T[u2];
    const int bf = g & 1;
    load_xq(sb + SM_XS + bf * 16384,
            g_xh + (size_t)r0 * NFEAT + s2 * FDIM + q2 * 64, p, h, lane);
    load_vq(sb + SM_VS + (bf * 2 + h) * 4096,
            g_vh + (size_t)((s2 * NFIELDS + t2) * NL + h * 32) * FDIM + q2 * 64, p, lane);
    if (s2 != t2) {
        load_xq(sb + SM_XT + bf * 16384,
                g_xh + (size_t)r0 * NFEAT + t2 * FDIM + q2 * 64, p, h, lane);
        load_vq(sb + SM_VT + (bf * 2 + h) * 4096,
                g_vh + (size_t)((t2 * NFIELDS + s2) * NL + h * 32) * FDIM + q2 * 64, p, lane);
    }
    CP_COMMIT();
}

// Quarter GEMM: acc += X_q(warp's 32 rows x 64k) @ V_halfq^T   (m32 x n32 x k64)
static __device__ __forceinline__ void gemm32(uint32_t sx, uint32_t sv,
                                              int p, int lane, float acc[2][4][4]) {
    const int arow = p * 32 + (lane & 15);
    const int ak = ((lane >> 4) << 3) * 2;
    const int brow = ((lane >> 4) << 3) + (lane & 7);
    const int bk = (((lane >> 3) & 1) << 3) * 2;
    #pragma unroll
    for (int k4 = 0; k4 < 4; ++k4) {
        const int kb = k4 * 32;
        uint32_t a00, a01, a02, a03, a10, a11, a12, a13;
        ldmx4(sx + SW128(arow * 128 + kb + ak), a00, a01, a02, a03);
        ldmx4(sx + SW128((arow + 16) * 128 + kb + ak), a10, a11, a12, a13);
        #pragma unroll
        for (int vt = 0; vt < 2; ++vt) {
            uint32_t b0, b1, b2, b3;
            ldmx4(sv + SW128((vt * 16 + brow) * 128 + kb + bk), b0, b1, b2, b3);
            mma16816(acc[0][2 * vt],     a00, a01, a02, a03, b0, b1);
            mma16816(acc[0][2 * vt + 1], a00, a01, a02, a03, b2, b3);
            mma16816(acc[1][2 * vt],     a10, a11, a12, a13, b0, b1);
            mma16816(acc[1][2 * vt + 1], a10, a11, a12, a13, b2, b3);
        }
    }
}

static __device__ __forceinline__ void zero4(float acc[2][4][4]) {
    #pragma unroll
    for (int m = 0; m < 2; ++m)
        #pragma unroll
        for (int n = 0; n < 4; ++n)
            #pragma unroll
            for (int j = 0; j < 4; ++j) acc[m][n][j] = 0.f;
}

__global__ __launch_bounds__(NTHREADS, 2)
void ffm_main(const float* __restrict__ w, float* __restrict__ out) {
    extern __shared__ char smem[];
    const uint32_t sb = smem_u32(smem);
    const int tid = threadIdx.x;
    const int wrp = tid >> 5;
    const int lane = tid & 31;
    const int p = wrp >> 1;          // pair (m-tile) 0..3
    const int h = wrp & 1;           // n-half 0..1
    const int r0 = blockIdx.x * ROWT;
    const int u0 = blockIdx.y * 4;
    float* dks = (float*)(smem + SM_DKS);

    const int bar_p = 1 + p, bar_h = 5 + h;

    // pipeline prologue: stage 0 only (depth-1; each load covered by one gemm stage)
    issue_stage(sb, r0, p, h, lane, u0, 0);

    // dks for this group's diag unit (always at uu==3 when present) -- overlaps prologue
    {
        const int ud = u0 + 3;
        const int sd = U_S[ud];
        if (sd == U_T[ud]) {
            const __half* vp = g_vh + (size_t)((sd * NFIELDS + sd) * NL) * FDIM + tid;
            float a = 0.f;
            #pragma unroll 8
            for (int l = 0; l < NL; ++l) {
                float f = __half2float(vp[(size_t)l * FDIM]);
                a += f * f;
            }
            dks[tid] = a;
        }
    }
    __syncthreads();   // dks visible for the whole kernel

    float acc_int[4] = {0.f, 0.f, 0.f, 0.f};   // row = p*32 + (lane>>2) + slot*8

    for (int uu = 0; uu < 4; ++uu) {
        const int u = u0 + uu;
        const int s = U_S[u], t = U_T[u];

        float a1[2][4][4];
        zero4(a1);
        float p4[4] = {0.f, 0.f, 0.f, 0.f};

        if (s != t) {
            float a2[2][4][4];
            zero4(a2);
            #pragma unroll
            for (int q = 0; q < 4; ++q) {
                const int g = uu * 4 + q;
                CP_WAIT0();                              // stage g data arrived
                BARX(bar_p, 64); BARX(bar_h, 128);       // visible + prior-gemm buffer free
                if (g + 1 < 16) issue_stage(sb, r0, p, h, lane, u0, g + 1);
                const int bf = g & 1;
                gemm32(sb + SM_XS + bf * 16384, sb + SM_VS + (bf * 2 + h) * 4096, p, lane, a1);
                gemm32(sb + SM_XT + bf * 16384, sb + SM_VT + (bf * 2 + h) * 4096, p, lane, a2);
            }
            // dot(M1, M2), counted twice (ordered pairs)
            #pragma unroll
            for (int mf = 0; mf < 2; ++mf)
                #pragma unroll
                for (int nf = 0; nf < 4; ++nf) {
                    p4[mf * 2 + 0] += a1[mf][nf][0] * a2[mf][nf][0] +
                                      a1[mf][nf][1] * a2[mf][nf][1];
                    p4[mf * 2 + 1] += a1[mf][nf][2] * a2[mf][nf][2] +
                                      a1[mf][nf][3] * a2[mf][nf][3];
                }
            #pragma unroll
            for (int i = 0; i < 4; ++i) p4[i] *= 2.f;
        } else {
            // diag unit (uu==3): gemm + q/linear per quarter; dks precomputed
            float dql[4] = {0.f, 0.f, 0.f, 0.f};
            const float* wp = w + s * FDIM;
            #pragma unroll
            for (int q = 0; q < 4; ++q) {
                const int g = uu * 4 + q;
                CP_WAIT0();
                BARX(bar_p, 64); BARX(bar_h, 128);
                if (g + 1 < 16) issue_stage(sb, r0, p, h, lane, u0, g + 1);
                const int bf = g & 1;
                gemm32(sb + SM_XS + bf * 16384, sb + SM_VS + (bf * 2 + h) * 4096, p, lane, a1);
                {
                    const char* xsm = smem + SM_XS + bf * 16384;
                    const int kin0 = h * 32 + (lane & 3) * 8;
                    const int rb = p * 32 + (lane >> 2);
                    const float* dq = dks + q * 64;
                    const float* wq = wp + q * 64;
                    #pragma unroll
                    for (int i = 0; i < 8; ++i) {
                        int k = kin0 + i;
                        float dk = dq[k];
                        float wv = __ldg(wq + k);
                        #pragma unroll
                        for (int sl = 0; sl < 4; ++sl) {
                            float xv = __half2float(*(const __half*)(
                                xsm + SW128((rb + sl * 8) * 128 + k * 2)));
                            dql[sl] += xv * (4.f * wv - xv * dk);
                        }
                    }
                }
            }
            // self dot - q + 4*linear
            #pragma unroll
            for (int mf = 0; mf < 2; ++mf)
                #pragma unroll
                for (int nf = 0; nf < 4; ++nf) {
                    p4[mf * 2 + 0] += a1[mf][nf][0] * a1[mf][nf][0] +
                                      a1[mf][nf][1] * a1[mf][nf][1];
                    p4[mf * 2 + 1] += a1[mf][nf][2] * a1[mf][nf][2] +
                                      a1[mf][nf][3] * a1[mf][nf][3];
                }
            #pragma unroll
            for (int i = 0; i < 4; ++i) p4[i] += dql[i];
        }

        // reduce over 4 lanes sharing each row; accumulate
        #pragma unroll
        for (int i = 0; i < 4; ++i) {
            p4[i] += __shfl_xor_sync(0xFFFFFFFFu, p4[i], 1);
            p4[i] += __shfl_xor_sync(0xFFFFFFFFu, p4[i], 2);
            acc_int[i] += p4[i];
        }
    }

    if ((lane & 3) == 0) {
        #pragma unroll
        for (int sl = 0; sl < 4; ++sl) {
            int row = r0 + p * 32 + (lane >> 2) + sl * 8;
            atomicAdd(out + row, 0.25f * acc_int[sl]);
        }
    }
}

// ------------------------------------------------------------------
extern "C" void kernel_launch(void* const* d_in, const int* in_sizes, int n_in,
                              void* d_out, int out_size) {
    const float* x = (const float*)d_in[0];
    const float* b = (const float*)d_in[1];
    const float* w = (const float*)d_in[2];
    const float* V = (const float*)d_in[3];
    float* out = (float*)d_out;

    cudaFuncSetAttribute(ffm_main, cudaFuncAttributeMaxDynamicSharedMemorySize, SM_TOTAL);

    {
        size_t n16 = (size_t)NBATCH * NFEAT / 16;   // 1048576 threads cover x, V, out
        k_prep<<<(unsigned)((n16 + 255) / 256), 256>>>(x, V, b, out);
    }
    ffm_main<<<dim3(NBATCH / ROWT, 9), NTHREADS, SM_TOTAL>>>(w, out);
}

// round 17
// speedup vs baseline: 1.8329x; 1.0782x over previous
#include <cuda_runtime.h>
#include <cuda_fp16.h>
#include <cstdint>

#define NFEAT   2048
#define NBATCH  8192
#define NFIELDS 8
#define FDIM    256
#define NL      64
#define ROWT    128
#define NTHREADS 256

// fp16 scratch (static device arrays -- no runtime allocation)
__device__ __half g_xh[(size_t)NBATCH * NFEAT];              // 32 MB, row-major [B, F]
__device__ __half g_vh[NFIELDS * NFIELDS * NL * FDIM];        // 2 MB, [s][t][l][k]

// ---------------- SMEM layout (97 KB -> 2 CTAs/SM) ----------------
#define SM_DKS  0
#define SM_XS   1024
#define SM_XT   (SM_XS + 32768)
#define SM_VS   (SM_XT + 32768)
#define SM_VT   (SM_VS + 16384)
#define SM_TOTAL (SM_VT + 16384)   // 99328 B

#define SW128(off) ((off) ^ (((off) >> 3) & 0x70))

static __device__ __forceinline__ uint32_t smem_u32(const void* p) {
    uint32_t a;
    asm("{ .reg .u64 t; cvta.to.shared.u64 t, %1; cvt.u32.u64 %0, t; }" : "=r"(a) : "l"(p));
    return a;
}

#define CP_ASYNC16(dst, src) \
    asm volatile("cp.async.cg.shared.global [%0], [%1], 16;" :: "r"(dst), "l"(src))
#define CP_COMMIT() asm volatile("cp.async.commit_group;" ::: "memory")
#define CP_WAIT0()  asm volatile("cp.async.wait_group 0;" ::: "memory")

static __device__ __forceinline__ void ldmx4(uint32_t addr, uint32_t& r0, uint32_t& r1,
                                             uint32_t& r2, uint32_t& r3) {
    asm volatile("ldmatrix.sync.aligned.m8n8.x4.shared.b16 {%0,%1,%2,%3}, [%4];"
                 : "=r"(r0), "=r"(r1), "=r"(r2), "=r"(r3) : "r"(addr));
}

static __device__ __forceinline__ void mma16816(float* d, uint32_t a0, uint32_t a1,
                                                uint32_t a2, uint32_t a3,
                                                uint32_t b0, uint32_t b1) {
    asm volatile(
        "mma.sync.aligned.m16n8k16.row.col.f32.f16.f16.f32 "
        "{%0,%1,%2,%3}, {%4,%5,%6,%7}, {%8,%9}, {%0,%1,%2,%3};"
        : "+f"(d[0]), "+f"(d[1]), "+f"(d[2]), "+f"(d[3])
        : "r"(a0), "r"(a1), "r"(a2), "r"(a3), "r"(b0), "r"(b1));
}

// Balanced unit groups: g0 = 4 pairs; g1..g8 = 3 pairs + 1 diag (diag ALWAYS at uu==3)
__device__ const signed char U_S[36] = {
    0,0,0,0,  0,0,0,0,  1,1,1,1,  1,1,1,2,  2,2,2,3,  2,2,3,4,  3,3,3,5,  4,4,4,6,  5,5,6,7};
__device__ const signed char U_T[36] = {
    1,2,3,4,  5,6,7,0,  2,3,4,1,  5,6,7,2,  3,4,5,3,  6,7,4,4,  5,6,7,5,  5,6,7,6,  6,7,7,7};

// ------------------------------------------------------------------
// merged prepass: x -> fp16 (16 floats/thread), V -> fp16 transposed, out <- b
__global__ void k_prep(const float* __restrict__ x, const float* __restrict__ V,
                       const float* __restrict__ b, float* __restrict__ out) {
    size_t i = (size_t)blockIdx.x * blockDim.x + threadIdx.x;   // 1048576 threads

    size_t n16 = (size_t)NBATCH * NFEAT / 16;
    if (i < n16) {
        const float4* src = (const float4*)x + 4 * i;
        uint4* dst = (uint4*)g_xh + 2 * i;
        #pragma unroll
        for (int j = 0; j < 2; ++j) {
            float4 f0 = src[2 * j], f1 = src[2 * j + 1];
            __half2 h0 = __floats2half2_rn(f0.x, f0.y);
            __half2 h1 = __floats2half2_rn(f0.z, f0.w);
            __half2 h2 = __floats2half2_rn(f1.x, f1.y);
            __half2 h3 = __floats2half2_rn(f1.z, f1.w);
            uint4 o;
            o.x = *(uint32_t*)&h0; o.y = *(uint32_t*)&h1;
            o.z = *(uint32_t*)&h2; o.w = *(uint32_t*)&h3;
            dst[j] = o;
        }
    }
    if (i < (size_t)(NFEAT * NFIELDS * NL)) {
        int idx = (int)i;
        int f = idx / (NFIELDS * NL);
        int rest = idx % (NFIELDS * NL);
        int t = rest / NL, l = rest % NL;
        int s = f >> 8, k = f & 255;
        g_vh[(((s * NFIELDS + t) * NL) + l) * FDIM + k] = __float2half_rn(V[idx]);
    }
    if (i < NBATCH) out[i] = b[0];
}

// ------------------------------------------------------------------
// X quarter slice for this thread's pair: rows p*32+h*16..+16 x 128B; 4 x 16B per thread
static __device__ __forceinline__ void load_xq(uint32_t sbuf, const __half* gsrc,
                                               int p, int h, int lane) {
    #pragma unroll
    for (int it = 0; it < 4; ++it) {
        int tsk = lane + it * 32;                 // 0..127
        int row = p * 32 + h * 16 + (tsk >> 3);
        int c = tsk & 7;
        uint32_t sa = sbuf + SW128(row * 128 + c * 16);
        const char* ga = (const char*)gsrc + (size_t)row * (NFEAT * 2) + c * 16;
        CP_ASYNC16(sa, ga);
    }
}

// V half-quarter for this h-group: 32 l-rows x 128B; 2 x 16B per thread
static __device__ __forceinline__ void load_vq(uint32_t sbuf, const __half* gsrc,
                                               int p, int lane) {
    #pragma unroll
    for (int it = 0; it < 2; ++it) {
        int tsk = p * 32 + lane + it * 128;       // 0..255, disjoint across h-group
        int row = tsk >> 3;
        int c = tsk & 7;
        uint32_t sa = sbuf + SW128(row * 128 + c * 16);
        const char* ga = (const char*)gsrc + (size_t)row * (FDIM * 2) + c * 16;
        CP_ASYNC16(sa, ga);
    }
}

// issue all cp.asyncs for global pipeline stage g = u*4+q within this y-group, + commit.
static __device__ __forceinline__ void issue_stage(uint32_t sb, int r0, int p, int h,
                                                   int lane, int u0, int g) {
    const int u2 = u0 + (g >> 2), q2 = g & 3;
    const int s2 = U_S[u2], t2 = U_T[u2];
    const int bf = g & 1;
    load_xq(sb + SM_XS + bf * 16384,
            g_xh + (size_t)r0 * NFEAT + s2 * FDIM + q2 * 64, p, h, lane);
    load_vq(sb + SM_VS + (bf * 2 + h) * 4096,
            g_vh + (size_t)((s2 * NFIELDS + t2) * NL + h * 32) * FDIM + q2 * 64, p, lane);
    if (s2 != t2) {
        load_xq(sb + SM_XT + bf * 16384,
                g_xh + (size_t)r0 * NFEAT + t2 * FDIM + q2 * 64, p, h, lane);
        load_vq(sb + SM_VT + (bf * 2 + h) * 4096,
                g_vh + (size_t)((t2 * NFIELDS + s2) * NL + h * 32) * FDIM + q2 * 64, p, lane);
    }
    CP_COMMIT();
}

// Quarter GEMM: acc += X_q(warp's 32 rows x 64k) @ V_halfq^T   (m32 x n32 x k64)
static __device__ __forceinline__ void gemm32(uint32_t sx, uint32_t sv,
                                              int p, int lane, float acc[2][4][4]) {
    const int arow = p * 32 + (lane & 15);
    const int ak = ((lane >> 4) << 3) * 2;
    const int brow = ((lane >> 4) << 3) + (lane & 7);
    const int bk = (((lane >> 3) & 1) << 3) * 2;
    #pragma unroll
    for (int k4 = 0; k4 < 4; ++k4) {
        const int kb = k4 * 32;
        uint32_t a00, a01, a02, a03, a10, a11, a12, a13;
        ldmx4(sx + SW128(arow * 128 + kb + ak), a00, a01, a02, a03);
        ldmx4(sx + SW128((arow + 16) * 128 + kb + ak), a10, a11, a12, a13);
        #pragma unroll
        for (int vt = 0; vt < 2; ++vt) {
            uint32_t b0, b1, b2, b3;
            ldmx4(sv + SW128((vt * 16 + brow) * 128 + kb + bk), b0, b1, b2, b3);
            mma16816(acc[0][2 * vt],     a00, a01, a02, a03, b0, b1);
            mma16816(acc[0][2 * vt + 1], a00, a01, a02, a03, b2, b3);
            mma16816(acc[1][2 * vt],     a10, a11, a12, a13, b0, b1);
            mma16816(acc[1][2 * vt + 1], a10, a11, a12, a13, b2, b3);
        }
    }
}

// Dual quarter GEMM for pair units: chains interleaved at k4 granularity so the
// second chain's LDSMs overlap the first chain's MMAs.
static __device__ __forceinline__ void gemm32x2(uint32_t sxs, uint32_t svs,
                                                uint32_t sxt, uint32_t svt,
                                                int p, int lane,
                                                float a1[2][4][4], float a2[2][4][4]) {
    const int arow = p * 32 + (lane & 15);
    const int ak = ((lane >> 4) << 3) * 2;
    const int brow = ((lane >> 4) << 3) + (lane & 7);
    const int bk = (((lane >> 3) & 1) << 3) * 2;
    #pragma unroll
    for (int k4 = 0; k4 < 4; ++k4) {
        const int kb = k4 * 32;
        // chain 1
        {
            uint32_t a00, a01, a02, a03, a10, a11, a12, a13;
            ldmx4(sxs + SW128(arow * 128 + kb + ak), a00, a01, a02, a03);
            ldmx4(sxs + SW128((arow + 16) * 128 + kb + ak), a10, a11, a12, a13);
            #pragma unroll
            for (int vt = 0; vt < 2; ++vt) {
                uint32_t b0, b1, b2, b3;
                ldmx4(svs + SW128((vt * 16 + brow) * 128 + kb + bk), b0, b1, b2, b3);
                mma16816(a1[0][2 * vt],     a00, a01, a02, a03, b0, b1);
                mma16816(a1[0][2 * vt + 1], a00, a01, a02, a03, b2, b3);
                mma16816(a1[1][2 * vt],     a10, a11, a12, a13, b0, b1);
                mma16816(a1[1][2 * vt + 1], a10, a11, a12, a13, b2, b3);
            }
        }
        // chain 2 (independent; overlaps chain 1's MMA tail)
        {
            uint32_t a00, a01, a02, a03, a10, a11, a12, a13;
            ldmx4(sxt + SW128(arow * 128 + kb + ak), a00, a01, a02, a03);
            ldmx4(sxt + SW128((arow + 16) * 128 + kb + ak), a10, a11, a12, a13);
            #pragma unroll
            for (int vt = 0; vt < 2; ++vt) {
                uint32_t b0, b1, b2, b3;
                ldmx4(svt + SW128((vt * 16 + brow) * 128 + kb + bk), b0, b1, b2, b3);
                mma16816(a2[0][2 * vt],     a00, a01, a02, a03, b0, b1);
                mma16816(a2[0][2 * vt + 1], a00, a01, a02, a03, b2, b3);
                mma16816(a2[1][2 * vt],     a10, a11, a12, a13, b0, b1);
                mma16816(a2[1][2 * vt + 1], a10, a11, a12, a13, b2, b3);
            }
        }
    }
}

static __device__ __forceinline__ void zero4(float acc[2][4][4]) {
    #pragma unroll
    for (int m = 0; m < 2; ++m)
        #pragma unroll
        for (int n = 0; n < 4; ++n)
            #pragma unroll
            for (int j = 0; j < 4; ++j) acc[m][n][j] = 0.f;
}

__global__ __launch_bounds__(NTHREADS, 2)
void ffm_main(const float* __restrict__ w, float* __restrict__ out) {
    extern __shared__ char smem[];
    const uint32_t sb = smem_u32(smem);
    const int tid = threadIdx.x;
    const int wrp = tid >> 5;
    const int lane = tid & 31;
    const int p = wrp >> 1;          // pair (m-tile) 0..3
    const int h = wrp & 1;           // n-half 0..1
    const int r0 = blockIdx.x * ROWT;
    const int u0 = blockIdx.y * 4;
    float* dks = (float*)(smem + SM_DKS);

    // pipeline prologue: stage 0 (depth-1)
    issue_stage(sb, r0, p, h, lane, u0, 0);

    // dks for this group's diag unit (always at uu==3 when present) -- overlaps prologue
    {
        const int ud = u0 + 3;
        const int sd = U_S[ud];
        if (sd == U_T[ud]) {
            const __half* vp = g_vh + (size_t)((sd * NFIELDS + sd) * NL) * FDIM + tid;
            float a = 0.f;
            #pragma unroll 8
            for (int l = 0; l < NL; ++l) {
                float f = __half2float(vp[(size_t)l * FDIM]);
                a += f * f;
            }
            dks[tid] = a;
        }
    }
    __syncthreads();   // dks visible for the whole kernel

    float acc_int[4] = {0.f, 0.f, 0.f, 0.f};   // row = p*32 + (lane>>2) + slot*8

    for (int uu = 0; uu < 4; ++uu) {
        const int u = u0 + uu;
        const int s = U_S[u], t = U_T[u];

        float a1[2][4][4];
        zero4(a1);
        float p4[4] = {0.f, 0.f, 0.f, 0.f};

        if (s != t) {
            float a2[2][4][4];
            zero4(a2);
            #pragma unroll
            for (int q = 0; q < 4; ++q) {
                const int g = uu * 4 + q;
                CP_WAIT0();                              // stage g data arrived
                __syncthreads();                         // visible + prior buffer free
                if (g + 1 < 16) issue_stage(sb, r0, p, h, lane, u0, g + 1);
                const int bf = g & 1;
                gemm32x2(sb + SM_XS + bf * 16384, sb + SM_VS + (bf * 2 + h) * 4096,
                         sb + SM_XT + bf * 16384, sb + SM_VT + (bf * 2 + h) * 4096,
                         p, lane, a1, a2);
            }
            // dot(M1, M2), counted twice (ordered pairs)
            #pragma unroll
            for (int mf = 0; mf < 2; ++mf)
                #pragma unroll
                for (int nf = 0; nf < 4; ++nf) {
                    p4[mf * 2 + 0] += a1[mf][nf][0] * a2[mf][nf][0] +
                                      a1[mf][nf][1] * a2[mf][nf][1];
                    p4[mf * 2 + 1] += a1[mf][nf][2] * a2[mf][nf][2] +
                                      a1[mf][nf][3] * a2[mf][nf][3];
                }
            #pragma unroll
            for (int i = 0; i < 4; ++i) p4[i] *= 2.f;
        } else {
            // diag unit (uu==3): gemm + q/linear per quarter; dks precomputed
            float dql[4] = {0.f, 0.f, 0.f, 0.f};
            const float* wp = w + s * FDIM;
            #pragma unroll
            for (int q = 0; q < 4; ++q) {
                const int g = uu * 4 + q;
                CP_WAIT0();
                __syncthreads();
                if (g + 1 < 16) issue_stage(sb, r0, p, h, lane, u0, g + 1);
                const int bf = g & 1;
                gemm32(sb + SM_XS + bf * 16384, sb + SM_VS + (bf * 2 + h) * 4096, p, lane, a1);
                {
                    const char* xsm = smem + SM_XS + bf * 16384;
                    const int kin0 = h * 32 + (lane & 3) * 8;   // 8 consecutive k's, 16B aligned
                    const int rb = p * 32 + (lane >> 2);
                    const float* dq = dks + q * 64;
                    const float* wq = wp + q * 64;
                    #pragma unroll
                    for (int sl = 0; sl < 4; ++sl) {
                        const int row = rb + sl * 8;
                        uint4 v = *(const uint4*)(xsm + SW128(row * 128 + kin0 * 2));
                        const uint32_t* vv = (const uint32_t*)&v;
                        float acc_sl = 0.f;
                        #pragma unroll
                        for (int j = 0; j < 4; ++j) {
                            float2 xp = __half22float2(*(const __half2*)&vv[j]);
                            int k0 = kin0 + 2 * j;
                            acc_sl += xp.x * (4.f * __ldg(wq + k0)     - xp.x * dq[k0]);
                            acc_sl += xp.y * (4.f * __ldg(wq + k0 + 1) - xp.y * dq[k0 + 1]);
                        }
                        dql[sl] += acc_sl;
                    }
                }
            }
            // self dot - q + 4*linear
            #pragma unroll
            for (int mf = 0; mf < 2; ++mf)
                #pragma unroll
                for (int nf = 0; nf < 4; ++nf) {
                    p4[mf * 2 + 0] += a1[mf][nf][0] * a1[mf][nf][0] +
                                      a1[mf][nf][1] * a1[mf][nf][1];
                    p4[mf * 2 + 1] += a1[mf][nf][2] * a1[mf][nf][2] +
                                      a1[mf][nf][3] * a1[mf][nf][3];
                }
            #pragma unroll
            for (int i = 0; i < 4; ++i) p4[i] += dql[i];
        }

        // reduce over 4 lanes sharing each row; accumulate
        #pragma unroll
        for (int i = 0; i < 4; ++i) {
            p4[i] += __shfl_xor_sync(0xFFFFFFFFu, p4[i], 1);
            p4[i] += __shfl_xor_sync(0xFFFFFFFFu, p4[i], 2);
            acc_int[i] += p4[i];
        }
    }

    if ((lane & 3) == 0) {
        #pragma unroll
        for (int sl = 0; sl < 4; ++sl) {
            int row = r0 + p * 32 + (lane >> 2) + sl * 8;
            atomicAdd(out + row, 0.25f * acc_int[sl]);
        }
    }
}

// ------------------------------------------------------------------
extern "C" void kernel_launch(void* const* d_in, const int* in_sizes, int n_in,
                              void* d_out, int out_size) {
    const float* x = (const float*)d_in[0];
    const float* b = (const float*)d_in[1];
    const float* w = (const float*)d_in[2];
    const float* V = (const float*)d_in[3];
    float* out = (float*)d_out;

    cudaFuncSetAttribute(ffm_main, cudaFuncAttributeMaxDynamicSharedMemorySize, SM_TOTAL);

    {
        size_t n16 = (size_t)NBATCH * NFEAT / 16;   // 1048576 threads cover x, V, out
        k_prep<<<(unsigned)((n16 + 255) / 256), 256>>>(x, V, b, out);
    }
    ffm_main<<<dim3(NBATCH / ROWT, 9), NTHREADS, SM_TOTAL>>>(w, out);
}